// round 1
// baseline (speedup 1.0000x reference)
#include <cuda_runtime.h>
#include <math.h>

#define NOBJ 50000
#define NTRI 100000
#define DIN_ 128
#define H_   512
#define DOUT_ 128

// ---------------- scratch (device globals: no allocs allowed) ----------------
static __device__ float    g_h1[(size_t)NTRI * H_];        // relu(t_in@w1+b1)      204.8MB
static __device__ float    g_cand[(size_t)2 * NTRI * H_];  // [new_s ; new_o]       409.6MB
static __device__ float    g_prev[(size_t)NOBJ * H_];      // obj@proj_w+b          102.4MB
static __device__ float    g_pp[(size_t)NOBJ * H_];        // prev_proj             102.4MB
static __device__ float    g_u[(size_t)NOBJ * H_];         // prev_proj @ sim_w^T   102.4MB
static __device__ float    g_z[NOBJ];                      // zero_scores
static __device__ unsigned g_mkey[NOBJ];                   // encoded running max
static __device__ float    g_scores[2 * NTRI];
static __device__ float    g_w[2 * NTRI];
static __device__ float    g_denom[NOBJ];
static __device__ float    g_pooled[(size_t)NOBJ * H_];    // 102.4MB
static __device__ float    g_h2[(size_t)NOBJ * H_];        // 102.4MB

// monotone float<->uint encoding for atomicMax on floats
__device__ __forceinline__ unsigned fenc(float f) {
    unsigned u = __float_as_uint(f);
    return (u & 0x80000000u) ? ~u : (u | 0x80000000u);
}
__device__ __forceinline__ float fdec(unsigned e) {
    unsigned u = (e & 0x80000000u) ? (e & 0x7fffffffu) : ~e;
    return __uint_as_float(u);
}

// ---------------- generic 128x128x8 fp32 tiled GEMM ----------------
// AMODE: 0 plain A[M,K]; 1 gather rows = [obj[s],pred,obj[o]] (K=384); 2 plain scaled by 1/denom[m]
// BMODE: 0 B[K,N] row-major; 1 B is [N,K] row-major, use B^T (B_log[k][n] = B[n*K+k])
// CMODE: 0 plain C[M,N]; 1 split (N=1152): n<512 -> cand[m], 512..639 -> outp[m], >=640 -> cand[T+m]
template<int AMODE, int BMODE, int CMODE, bool RELU, bool HASBIAS>
__global__ __launch_bounds__(256, 2)
void gemm_k(const float* __restrict__ A, const float* __restrict__ B,
            const float* __restrict__ bias, float* __restrict__ C,
            int M, int N, int K,
            const float* __restrict__ obj, const float* __restrict__ pred,
            const int* __restrict__ edges, const float* __restrict__ denomv,
            float* __restrict__ outp, float* __restrict__ candp)
{
    __shared__ float As[8][128];
    __shared__ float Bs[8][128];

    const int tid = threadIdx.x;
    const int bm = blockIdx.y * 128;
    const int bn = blockIdx.x * 128;

    // A load mapping: 128 rows x 8 k = 256 float4; row = tid/2, k-quad = (tid&1)*4
    const int a_r  = tid >> 1;
    const int a_k4 = (tid & 1) << 2;
    const int am   = bm + a_r;

    int gs = 0, go = 0;
    if (AMODE == 1 && am < M) { gs = edges[2 * am]; go = edges[2 * am + 1]; }
    float ascale = 1.0f;
    if (AMODE == 2 && am < M) ascale = __fdividef(1.0f, denomv[am]);

    // B load mapping
    const int b_k   = tid >> 5;          // BMODE0: 0..7
    const int b_n4  = (tid & 31) << 2;   // BMODE0: 0..124
    const int bt_n  = tid >> 1;          // BMODE1: 0..127
    const int bt_k4 = (tid & 1) << 2;    // BMODE1: 0 or 4

    auto fetchA = [&](int k0) -> float4 {
        if (am >= M) return make_float4(0.f, 0.f, 0.f, 0.f);
        const int kk = k0 + a_k4;
        const float* p;
        if (AMODE == 1) {
            if (kk < DIN_)          p = obj  + (size_t)gs * DIN_ + kk;
            else if (kk < 2 * DIN_) p = pred + (size_t)am * DIN_ + (kk - DIN_);
            else                    p = obj  + (size_t)go * DIN_ + (kk - 2 * DIN_);
        } else {
            p = A + (size_t)am * K + kk;
        }
        float4 v = *(const float4*)p;
        if (AMODE == 2) { v.x *= ascale; v.y *= ascale; v.z *= ascale; v.w *= ascale; }
        return v;
    };
    auto fetchB = [&](int k0) -> float4 {
        if (BMODE == 0) return *(const float4*)(B + (size_t)(k0 + b_k) * N + bn + b_n4);
        else            return *(const float4*)(B + (size_t)(bn + bt_n) * K + k0 + bt_k4);
    };

    float acc[8][8];
    #pragma unroll
    for (int i = 0; i < 8; i++)
        #pragma unroll
        for (int j = 0; j < 8; j++) acc[i][j] = 0.f;

    const int tx = tid & 15, ty = tid >> 4;

    float4 av = fetchA(0);
    float4 bv = fetchB(0);

    for (int k0 = 0; k0 < K; k0 += 8) {
        // stage to smem
        As[a_k4 + 0][a_r] = av.x; As[a_k4 + 1][a_r] = av.y;
        As[a_k4 + 2][a_r] = av.z; As[a_k4 + 3][a_r] = av.w;
        if (BMODE == 0) {
            *(float4*)&Bs[b_k][b_n4] = bv;
        } else {
            Bs[bt_k4 + 0][bt_n] = bv.x; Bs[bt_k4 + 1][bt_n] = bv.y;
            Bs[bt_k4 + 2][bt_n] = bv.z; Bs[bt_k4 + 3][bt_n] = bv.w;
        }
        __syncthreads();
        if (k0 + 8 < K) { av = fetchA(k0 + 8); bv = fetchB(k0 + 8); }

        #pragma unroll
        for (int k = 0; k < 8; k++) {
            float4 a0 = *(const float4*)&As[k][ty * 8];
            float4 a1 = *(const float4*)&As[k][ty * 8 + 4];
            float4 b0 = *(const float4*)&Bs[k][tx * 8];
            float4 b1 = *(const float4*)&Bs[k][tx * 8 + 4];
            float ar[8] = {a0.x, a0.y, a0.z, a0.w, a1.x, a1.y, a1.z, a1.w};
            float br[8] = {b0.x, b0.y, b0.z, b0.w, b1.x, b1.y, b1.z, b1.w};
            #pragma unroll
            for (int i = 0; i < 8; i++)
                #pragma unroll
                for (int j = 0; j < 8; j++)
                    acc[i][j] = fmaf(ar[i], br[j], acc[i][j]);
        }
        __syncthreads();
    }

    // epilogue
    const int n0 = bn + tx * 8;
    float bsv[8];
    #pragma unroll
    for (int j = 0; j < 8; j++) bsv[j] = HASBIAS ? bias[n0 + j] : 0.f;

    #pragma unroll
    for (int i = 0; i < 8; i++) {
        const int m = bm + ty * 8 + i;
        if (m >= M) break;
        float v[8];
        #pragma unroll
        for (int j = 0; j < 8; j++) {
            float x = acc[i][j] + bsv[j];
            v[j] = RELU ? fmaxf(x, 0.f) : x;
        }
        float* base;
        if (CMODE == 0) {
            base = C + (size_t)m * N + n0;
        } else {
            if (n0 < H_)              base = candp + (size_t)m * H_ + n0;
            else if (n0 < H_ + DOUT_) base = outp  + (size_t)m * DOUT_ + (n0 - H_);
            else                      base = candp + (size_t)(NTRI + m) * H_ + (n0 - H_ - DOUT_);
        }
        ((float4*)base)[0] = make_float4(v[0], v[1], v[2], v[3]);
        ((float4*)base)[1] = make_float4(v[4], v[5], v[6], v[7]);
    }
}

// z[i] = prev_proj[i] . sim_b ; seed mkey with enc(z) (so m = max(z, segmax) for free)
__global__ void zk(const float* __restrict__ pp, const float* __restrict__ simb,
                   float* __restrict__ z, unsigned* __restrict__ mkey)
{
    const int warp = (blockIdx.x * blockDim.x + threadIdx.x) >> 5;
    const int lane = threadIdx.x & 31;
    if (warp >= NOBJ) return;
    const float4* a = (const float4*)(pp + (size_t)warp * H_);
    const float4* b = (const float4*)simb;
    float s = 0.f;
    #pragma unroll
    for (int q = 0; q < 4; q++) {
        float4 x = a[lane + q * 32], y = b[lane + q * 32];
        s += x.x * y.x + x.y * y.y + x.z * y.z + x.w * y.w;
    }
    #pragma unroll
    for (int o = 16; o; o >>= 1) s += __shfl_down_sync(0xffffffffu, s, o);
    if (lane == 0) { z[warp] = s; mkey[warp] = fenc(s); }
}

// scores[e] = cand[e] . u[idx] + z[idx];  atomicMax into mkey[idx]
__global__ void scorek(const float* __restrict__ cand, const float* __restrict__ u,
                       const float* __restrict__ z, const int* __restrict__ edges,
                       float* __restrict__ scores, unsigned* __restrict__ mkey)
{
    const int e = (blockIdx.x * blockDim.x + threadIdx.x) >> 5;
    const int lane = threadIdx.x & 31;
    if (e >= 2 * NTRI) return;
    const int idx = (e < NTRI) ? edges[2 * e] : edges[2 * (e - NTRI) + 1];
    const float4* a = (const float4*)(cand + (size_t)e * H_);
    const float4* b = (const float4*)(u + (size_t)idx * H_);
    float s = 0.f;
    #pragma unroll
    for (int q = 0; q < 4; q++) {
        float4 x = a[lane + q * 32], y = b[lane + q * 32];
        s += x.x * y.x + x.y * y.y + x.z * y.z + x.w * y.w;
    }
    #pragma unroll
    for (int o = 16; o; o >>= 1) s += __shfl_down_sync(0xffffffffu, s, o);
    if (lane == 0) {
        const float sc = s + z[idx];
        scores[e] = sc;
        atomicMax(mkey + idx, fenc(sc));
    }
}

__global__ void zerok(float* __restrict__ p, size_t n)
{
    size_t i = (size_t)blockIdx.x * blockDim.x + threadIdx.x;
    const size_t stride = (size_t)gridDim.x * blockDim.x;
    for (; i < n; i += stride) p[i] = 0.f;
}

__global__ void dinitk(const float* __restrict__ z, const unsigned* __restrict__ mkey,
                       float* __restrict__ denom)
{
    const int i = blockIdx.x * blockDim.x + threadIdx.x;
    if (i < NOBJ) denom[i] = expf(z[i] - fdec(mkey[i]));
}

__global__ void wk(const float* __restrict__ scores, const unsigned* __restrict__ mkey,
                   const int* __restrict__ edges, float* __restrict__ w,
                   float* __restrict__ denom)
{
    const int e = blockIdx.x * blockDim.x + threadIdx.x;
    if (e >= 2 * NTRI) return;
    const int idx = (e < NTRI) ? edges[2 * e] : edges[2 * (e - NTRI) + 1];
    const float ww = expf(scores[e] - fdec(mkey[idx]));
    w[e] = ww;
    atomicAdd(denom + idx, ww);
}

// pooled[idx] += w[e] * cand[e]  (warp per edge)
__global__ void poolk(const float* __restrict__ cand, const float* __restrict__ w,
                      const int* __restrict__ edges, float* __restrict__ pooled)
{
    const int e = (blockIdx.x * blockDim.x + threadIdx.x) >> 5;
    const int lane = threadIdx.x & 31;
    if (e >= 2 * NTRI) return;
    const int idx = (e < NTRI) ? edges[2 * e] : edges[2 * (e - NTRI) + 1];
    const float ww = w[e];
    const float4* src = (const float4*)(cand + (size_t)e * H_);
    float* dst = pooled + (size_t)idx * H_;
    #pragma unroll
    for (int q = 0; q < 4; q++) {
        float4 v = src[lane + q * 32];
        float* d = dst + (size_t)(lane + q * 32) * 4;
        atomicAdd(d + 0, v.x * ww);
        atomicAdd(d + 1, v.y * ww);
        atomicAdd(d + 2, v.z * ww);
        atomicAdd(d + 3, v.w * ww);
    }
}

extern "C" void kernel_launch(void* const* d_in, const int* in_sizes, int n_in,
                              void* d_out, int out_size)
{
    const float* obj    = (const float*)d_in[0];
    const float* pred   = (const float*)d_in[1];
    const int*   edges  = (const int*)d_in[2];
    const float* n1_w1  = (const float*)d_in[3];
    const float* n1_b1  = (const float*)d_in[4];
    const float* n1_w2  = (const float*)d_in[5];
    const float* n1_b2  = (const float*)d_in[6];
    const float* n2_w1  = (const float*)d_in[7];
    const float* n2_b1  = (const float*)d_in[8];
    const float* n2_w2  = (const float*)d_in[9];
    const float* n2_b2  = (const float*)d_in[10];
    const float* proj_w = (const float*)d_in[11];
    const float* proj_b = (const float*)d_in[12];
    const float* sim_w  = (const float*)d_in[13];
    const float* sim_b  = (const float*)d_in[14];

    float* out        = (float*)d_out;
    float* out_newobj = out;
    float* out_newp   = out + (size_t)NOBJ * DOUT_;

    float *h1, *cand, *prev, *pp, *u, *z, *scores, *w, *denom, *pooled, *h2;
    unsigned* mkey;
    cudaGetSymbolAddress((void**)&h1, g_h1);
    cudaGetSymbolAddress((void**)&cand, g_cand);
    cudaGetSymbolAddress((void**)&prev, g_prev);
    cudaGetSymbolAddress((void**)&pp, g_pp);
    cudaGetSymbolAddress((void**)&u, g_u);
    cudaGetSymbolAddress((void**)&z, g_z);
    cudaGetSymbolAddress((void**)&mkey, g_mkey);
    cudaGetSymbolAddress((void**)&scores, g_scores);
    cudaGetSymbolAddress((void**)&w, g_w);
    cudaGetSymbolAddress((void**)&denom, g_denom);
    cudaGetSymbolAddress((void**)&pooled, g_pooled);
    cudaGetSymbolAddress((void**)&h2, g_h2);

    const dim3 blk(256);
    const int gO = (NOBJ + 127) / 128;   // 391
    const int gT = (NTRI + 127) / 128;   // 782

    // object-side projections
    gemm_k<0,0,0,false,true><<<dim3(4, gO), blk>>>(obj,  proj_w, proj_b, prev, NOBJ, H_, DIN_,
                                                   nullptr, nullptr, nullptr, nullptr, nullptr, nullptr);
    gemm_k<0,0,0,false,true><<<dim3(4, gO), blk>>>(prev, sim_w,  sim_b,  pp,   NOBJ, H_, H_,
                                                   nullptr, nullptr, nullptr, nullptr, nullptr, nullptr);
    gemm_k<0,1,0,false,false><<<dim3(4, gO), blk>>>(pp,  sim_w,  nullptr, u,   NOBJ, H_, H_,
                                                   nullptr, nullptr, nullptr, nullptr, nullptr, nullptr);
    zk<<<(NOBJ * 32 + 255) / 256, 256>>>(pp, sim_b, z, mkey);

    // triple MLP (gather fused into A-load; outputs split into cand / new_p)
    gemm_k<1,0,0,true,true><<<dim3(4, gT), blk>>>(nullptr, n1_w1, n1_b1, h1, NTRI, H_, 3 * DIN_,
                                                  obj, pred, edges, nullptr, nullptr, nullptr);
    gemm_k<0,0,1,true,true><<<dim3(9, gT), blk>>>(h1, n1_w2, n1_b2, nullptr, NTRI, 2 * H_ + DOUT_, H_,
                                                  nullptr, nullptr, nullptr, nullptr, out_newp, cand);

    // attention scores + segment softmax
    scorek<<<(2 * NTRI + 7) / 8, 256>>>(cand, u, z, edges, scores, mkey);
    zerok<<<2048, 256>>>(pooled, (size_t)NOBJ * H_);
    dinitk<<<(NOBJ + 255) / 256, 256>>>(z, mkey, denom);
    wk<<<(2 * NTRI + 255) / 256, 256>>>(scores, mkey, edges, w, denom);
    poolk<<<(2 * NTRI + 7) / 8, 256>>>(cand, w, edges, pooled);

    // output MLP (divide-by-denom fused into A-load)
    gemm_k<2,0,0,true,true><<<dim3(4, gO), blk>>>(pooled, n2_w1, n2_b1, h2, NOBJ, H_, H_,
                                                  nullptr, nullptr, nullptr, denom, nullptr, nullptr);
    gemm_k<0,0,0,true,true><<<dim3(1, gO), blk>>>(h2, n2_w2, n2_b2, out_newobj, NOBJ, DOUT_, H_,
                                                  nullptr, nullptr, nullptr, nullptr, nullptr, nullptr);
}

// round 2
// speedup vs baseline: 1.0576x; 1.0576x over previous
#include <cuda_runtime.h>
#include <math.h>

#define NOBJ 50000
#define NTRI 100000
#define DIN_ 128
#define H_   512
#define DOUT_ 128

// ---------------- scratch (device globals: no allocs allowed) ----------------
static __device__ float    g_h1[(size_t)NTRI * H_];        // relu(t_in@w1+b1)      204.8MB
static __device__ float    g_cand[(size_t)2 * NTRI * H_];  // [new_s ; new_o]       409.6MB
static __device__ float    g_prev[(size_t)NOBJ * H_];      // obj@proj_w+b          102.4MB
static __device__ float    g_pp[(size_t)NOBJ * H_];        // prev_proj             102.4MB
static __device__ float    g_u[(size_t)NOBJ * H_];         // prev_proj @ sim_w^T   102.4MB
static __device__ float    g_z[NOBJ];                      // zero_scores
static __device__ unsigned g_mkey[NOBJ];                   // encoded running max
static __device__ float    g_scores[2 * NTRI];
static __device__ float    g_w[2 * NTRI];
static __device__ float    g_denom[NOBJ];
static __device__ float    g_pooled[(size_t)NOBJ * H_];    // 102.4MB
static __device__ float    g_h2[(size_t)NOBJ * H_];        // 102.4MB

// monotone float<->uint encoding for atomicMax on floats
__device__ __forceinline__ unsigned fenc(float f) {
    unsigned u = __float_as_uint(f);
    return (u & 0x80000000u) ? ~u : (u | 0x80000000u);
}
__device__ __forceinline__ float fdec(unsigned e) {
    unsigned u = (e & 0x80000000u) ? (e & 0x7fffffffu) : ~e;
    return __uint_as_float(u);
}

// ---------------- packed f32x2 helpers (Blackwell FFMA2 via PTX) ----------------
__device__ __forceinline__ unsigned long long pack2(float x) {
    unsigned long long r;
    asm("mov.b64 %0, {%1, %1};" : "=l"(r) : "f"(x));
    return r;
}
__device__ __forceinline__ void ffma2(unsigned long long& d, unsigned long long a,
                                      unsigned long long b) {
    asm("fma.rn.f32x2 %0, %1, %2, %0;" : "+l"(d) : "l"(a), "l"(b));
}
__device__ __forceinline__ float2 unpack2(unsigned long long v) {
    float2 r;
    asm("mov.b64 {%0, %1}, %2;" : "=f"(r.x), "=f"(r.y) : "l"(v));
    return r;
}

// ---------------- generic 128x128x8 fp32 tiled GEMM (FFMA2 core) ----------------
// AMODE: 0 plain A[M,K]; 1 gather rows = [obj[s],pred,obj[o]] (K=384); 2 plain scaled by 1/denom[m]
// BMODE: 0 B[K,N] row-major; 1 B is [N,K] row-major, use B^T
// CMODE: 0 plain C[M,N]; 1 split (N=1152): n<512 -> cand[m], 512..639 -> outp[m], >=640 -> cand[T+m]
template<int AMODE, int BMODE, int CMODE, bool RELU, bool HASBIAS>
__global__ __launch_bounds__(256, 2)
void gemm_k(const float* __restrict__ A, const float* __restrict__ B,
            const float* __restrict__ bias, float* __restrict__ C,
            int M, int N, int K,
            const float* __restrict__ obj, const float* __restrict__ pred,
            const int* __restrict__ edges, const float* __restrict__ denomv,
            float* __restrict__ outp, float* __restrict__ candp)
{
    __shared__ float As[8][128];
    __shared__ float Bs[8][128];

    const int tid = threadIdx.x;
    const int bm = blockIdx.y * 128;
    const int bn = blockIdx.x * 128;

    // A load mapping: 128 rows x 8 k = 256 float4; row = tid/2, k-quad = (tid&1)*4
    const int a_r  = tid >> 1;
    const int a_k4 = (tid & 1) << 2;
    const int am   = bm + a_r;

    int gs = 0, go = 0;
    if (AMODE == 1 && am < M) { gs = edges[2 * am]; go = edges[2 * am + 1]; }
    float ascale = 1.0f;
    if (AMODE == 2 && am < M) ascale = __fdividef(1.0f, denomv[am]);

    // B load mapping
    const int b_k   = tid >> 5;          // BMODE0: 0..7
    const int b_n4  = (tid & 31) << 2;   // BMODE0: 0..124
    const int bt_n  = tid >> 1;          // BMODE1: 0..127
    const int bt_k4 = (tid & 1) << 2;    // BMODE1: 0 or 4

    auto fetchA = [&](int k0) -> float4 {
        if (am >= M) return make_float4(0.f, 0.f, 0.f, 0.f);
        const int kk = k0 + a_k4;
        const float* p;
        if (AMODE == 1) {
            if (kk < DIN_)          p = obj  + (size_t)gs * DIN_ + kk;
            else if (kk < 2 * DIN_) p = pred + (size_t)am * DIN_ + (kk - DIN_);
            else                    p = obj  + (size_t)go * DIN_ + (kk - 2 * DIN_);
        } else {
            p = A + (size_t)am * K + kk;
        }
        float4 v = *(const float4*)p;
        if (AMODE == 2) { v.x *= ascale; v.y *= ascale; v.z *= ascale; v.w *= ascale; }
        return v;
    };
    auto fetchB = [&](int k0) -> float4 {
        if (BMODE == 0) return *(const float4*)(B + (size_t)(k0 + b_k) * N + bn + b_n4);
        else            return *(const float4*)(B + (size_t)(bn + bt_n) * K + k0 + bt_k4);
    };

    // packed accumulators: acc2[i][j] holds columns (tx*8 + 2j, tx*8 + 2j + 1)
    unsigned long long acc2[8][4];
    #pragma unroll
    for (int i = 0; i < 8; i++)
        #pragma unroll
        for (int j = 0; j < 4; j++) acc2[i][j] = 0ull;

    const int tx = tid & 15, ty = tid >> 4;

    float4 av = fetchA(0);
    float4 bv = fetchB(0);

    for (int k0 = 0; k0 < K; k0 += 8) {
        // stage to smem
        As[a_k4 + 0][a_r] = av.x; As[a_k4 + 1][a_r] = av.y;
        As[a_k4 + 2][a_r] = av.z; As[a_k4 + 3][a_r] = av.w;
        if (BMODE == 0) {
            *(float4*)&Bs[b_k][b_n4] = bv;
        } else {
            Bs[bt_k4 + 0][bt_n] = bv.x; Bs[bt_k4 + 1][bt_n] = bv.y;
            Bs[bt_k4 + 2][bt_n] = bv.z; Bs[bt_k4 + 3][bt_n] = bv.w;
        }
        __syncthreads();
        if (k0 + 8 < K) { av = fetchA(k0 + 8); bv = fetchB(k0 + 8); }

        #pragma unroll
        for (int k = 0; k < 8; k++) {
            float4 a0 = *(const float4*)&As[k][ty * 8];
            float4 a1 = *(const float4*)&As[k][ty * 8 + 4];
            const unsigned long long* bp = (const unsigned long long*)&Bs[k][tx * 8];
            unsigned long long br[4];
            br[0] = bp[0]; br[1] = bp[1]; br[2] = bp[2]; br[3] = bp[3];
            float ar[8] = {a0.x, a0.y, a0.z, a0.w, a1.x, a1.y, a1.z, a1.w};
            #pragma unroll
            for (int i = 0; i < 8; i++) {
                const unsigned long long ad = pack2(ar[i]);
                #pragma unroll
                for (int j = 0; j < 4; j++) ffma2(acc2[i][j], ad, br[j]);
            }
        }
        __syncthreads();
    }

    // epilogue
    const int n0 = bn + tx * 8;
    float bsv[8];
    #pragma unroll
    for (int j = 0; j < 8; j++) bsv[j] = HASBIAS ? bias[n0 + j] : 0.f;

    #pragma unroll
    for (int i = 0; i < 8; i++) {
        const int m = bm + ty * 8 + i;
        if (m >= M) break;
        float v[8];
        #pragma unroll
        for (int j = 0; j < 4; j++) {
            float2 p = unpack2(acc2[i][j]);
            float x0 = p.x + bsv[2 * j];
            float x1 = p.y + bsv[2 * j + 1];
            v[2 * j]     = RELU ? fmaxf(x0, 0.f) : x0;
            v[2 * j + 1] = RELU ? fmaxf(x1, 0.f) : x1;
        }
        float* base;
        if (CMODE == 0) {
            base = C + (size_t)m * N + n0;
        } else {
            if (n0 < H_)              base = candp + (size_t)m * H_ + n0;
            else if (n0 < H_ + DOUT_) base = outp  + (size_t)m * DOUT_ + (n0 - H_);
            else                      base = candp + (size_t)(NTRI + m) * H_ + (n0 - H_ - DOUT_);
        }
        ((float4*)base)[0] = make_float4(v[0], v[1], v[2], v[3]);
        ((float4*)base)[1] = make_float4(v[4], v[5], v[6], v[7]);
    }
}

// z[i] = prev_proj[i] . sim_b ; seed mkey with enc(z) (so m = max(z, segmax) for free)
__global__ void zk(const float* __restrict__ pp, const float* __restrict__ simb,
                   float* __restrict__ z, unsigned* __restrict__ mkey)
{
    const int warp = (blockIdx.x * blockDim.x + threadIdx.x) >> 5;
    const int lane = threadIdx.x & 31;
    if (warp >= NOBJ) return;
    const float4* a = (const float4*)(pp + (size_t)warp * H_);
    const float4* b = (const float4*)simb;
    float s = 0.f;
    #pragma unroll
    for (int q = 0; q < 4; q++) {
        float4 x = a[lane + q * 32], y = b[lane + q * 32];
        s += x.x * y.x + x.y * y.y + x.z * y.z + x.w * y.w;
    }
    #pragma unroll
    for (int o = 16; o; o >>= 1) s += __shfl_down_sync(0xffffffffu, s, o);
    if (lane == 0) { z[warp] = s; mkey[warp] = fenc(s); }
}

// scores[e] = cand[e] . u[idx] + z[idx];  atomicMax into mkey[idx]
__global__ void scorek(const float* __restrict__ cand, const float* __restrict__ u,
                       const float* __restrict__ z, const int* __restrict__ edges,
                       float* __restrict__ scores, unsigned* __restrict__ mkey)
{
    const int e = (blockIdx.x * blockDim.x + threadIdx.x) >> 5;
    const int lane = threadIdx.x & 31;
    if (e >= 2 * NTRI) return;
    const int idx = (e < NTRI) ? edges[2 * e] : edges[2 * (e - NTRI) + 1];
    const float4* a = (const float4*)(cand + (size_t)e * H_);
    const float4* b = (const float4*)(u + (size_t)idx * H_);
    float s = 0.f;
    #pragma unroll
    for (int q = 0; q < 4; q++) {
        float4 x = a[lane + q * 32], y = b[lane + q * 32];
        s += x.x * y.x + x.y * y.y + x.z * y.z + x.w * y.w;
    }
    #pragma unroll
    for (int o = 16; o; o >>= 1) s += __shfl_down_sync(0xffffffffu, s, o);
    if (lane == 0) {
        const float sc = s + z[idx];
        scores[e] = sc;
        atomicMax(mkey + idx, fenc(sc));
    }
}

__global__ void zerok(float* __restrict__ p, size_t n)
{
    size_t i = (size_t)blockIdx.x * blockDim.x + threadIdx.x;
    const size_t stride = (size_t)gridDim.x * blockDim.x;
    for (; i < n; i += stride) p[i] = 0.f;
}

__global__ void dinitk(const float* __restrict__ z, const unsigned* __restrict__ mkey,
                       float* __restrict__ denom)
{
    const int i = blockIdx.x * blockDim.x + threadIdx.x;
    if (i < NOBJ) denom[i] = expf(z[i] - fdec(mkey[i]));
}

__global__ void wk(const float* __restrict__ scores, const unsigned* __restrict__ mkey,
                   const int* __restrict__ edges, float* __restrict__ w,
                   float* __restrict__ denom)
{
    const int e = blockIdx.x * blockDim.x + threadIdx.x;
    if (e >= 2 * NTRI) return;
    const int idx = (e < NTRI) ? edges[2 * e] : edges[2 * (e - NTRI) + 1];
    const float ww = expf(scores[e] - fdec(mkey[idx]));
    w[e] = ww;
    atomicAdd(denom + idx, ww);
}

// pooled[idx] += w[e] * cand[e]  (warp per edge, vector RED)
__global__ void poolk(const float* __restrict__ cand, const float* __restrict__ w,
                      const int* __restrict__ edges, float* __restrict__ pooled)
{
    const int e = (blockIdx.x * blockDim.x + threadIdx.x) >> 5;
    const int lane = threadIdx.x & 31;
    if (e >= 2 * NTRI) return;
    const int idx = (e < NTRI) ? edges[2 * e] : edges[2 * (e - NTRI) + 1];
    const float ww = w[e];
    const float4* src = (const float4*)(cand + (size_t)e * H_);
    float* dst = pooled + (size_t)idx * H_;
    #pragma unroll
    for (int q = 0; q < 4; q++) {
        float4 v = src[lane + q * 32];
        float* d = dst + (size_t)(lane + q * 32) * 4;
        asm volatile("red.global.add.v4.f32 [%0], {%1, %2, %3, %4};"
                     :: "l"(d), "f"(v.x * ww), "f"(v.y * ww), "f"(v.z * ww), "f"(v.w * ww)
                     : "memory");
    }
}

extern "C" void kernel_launch(void* const* d_in, const int* in_sizes, int n_in,
                              void* d_out, int out_size)
{
    const float* obj    = (const float*)d_in[0];
    const float* pred   = (const float*)d_in[1];
    const int*   edges  = (const int*)d_in[2];
    const float* n1_w1  = (const float*)d_in[3];
    const float* n1_b1  = (const float*)d_in[4];
    const float* n1_w2  = (const float*)d_in[5];
    const float* n1_b2  = (const float*)d_in[6];
    const float* n2_w1  = (const float*)d_in[7];
    const float* n2_b1  = (const float*)d_in[8];
    const float* n2_w2  = (const float*)d_in[9];
    const float* n2_b2  = (const float*)d_in[10];
    const float* proj_w = (const float*)d_in[11];
    const float* proj_b = (const float*)d_in[12];
    const float* sim_w  = (const float*)d_in[13];
    const float* sim_b  = (const float*)d_in[14];

    float* out        = (float*)d_out;
    float* out_newobj = out;
    float* out_newp   = out + (size_t)NOBJ * DOUT_;

    float *h1, *cand, *prev, *pp, *u, *z, *scores, *w, *denom, *pooled, *h2;
    unsigned* mkey;
    cudaGetSymbolAddress((void**)&h1, g_h1);
    cudaGetSymbolAddress((void**)&cand, g_cand);
    cudaGetSymbolAddress((void**)&prev, g_prev);
    cudaGetSymbolAddress((void**)&pp, g_pp);
    cudaGetSymbolAddress((void**)&u, g_u);
    cudaGetSymbolAddress((void**)&z, g_z);
    cudaGetSymbolAddress((void**)&mkey, g_mkey);
    cudaGetSymbolAddress((void**)&scores, g_scores);
    cudaGetSymbolAddress((void**)&w, g_w);
    cudaGetSymbolAddress((void**)&denom, g_denom);
    cudaGetSymbolAddress((void**)&pooled, g_pooled);
    cudaGetSymbolAddress((void**)&h2, g_h2);

    const dim3 blk(256);
    const int gO = (NOBJ + 127) / 128;   // 391
    const int gT = (NTRI + 127) / 128;   // 782

    // object-side projections
    gemm_k<0,0,0,false,true><<<dim3(4, gO), blk>>>(obj,  proj_w, proj_b, prev, NOBJ, H_, DIN_,
                                                   nullptr, nullptr, nullptr, nullptr, nullptr, nullptr);
    gemm_k<0,0,0,false,true><<<dim3(4, gO), blk>>>(prev, sim_w,  sim_b,  pp,   NOBJ, H_, H_,
                                                   nullptr, nullptr, nullptr, nullptr, nullptr, nullptr);
    gemm_k<0,1,0,false,false><<<dim3(4, gO), blk>>>(pp,  sim_w,  nullptr, u,   NOBJ, H_, H_,
                                                   nullptr, nullptr, nullptr, nullptr, nullptr, nullptr);
    zk<<<(NOBJ * 32 + 255) / 256, 256>>>(pp, sim_b, z, mkey);

    // triple MLP (gather fused into A-load; outputs split into cand / new_p)
    gemm_k<1,0,0,true,true><<<dim3(4, gT), blk>>>(nullptr, n1_w1, n1_b1, h1, NTRI, H_, 3 * DIN_,
                                                  obj, pred, edges, nullptr, nullptr, nullptr);
    gemm_k<0,0,1,true,true><<<dim3(9, gT), blk>>>(h1, n1_w2, n1_b2, nullptr, NTRI, 2 * H_ + DOUT_, H_,
                                                  nullptr, nullptr, nullptr, nullptr, out_newp, cand);

    // attention scores + segment softmax
    scorek<<<(2 * NTRI + 7) / 8, 256>>>(cand, u, z, edges, scores, mkey);
    zerok<<<2048, 256>>>(pooled, (size_t)NOBJ * H_);
    dinitk<<<(NOBJ + 255) / 256, 256>>>(z, mkey, denom);
    wk<<<(2 * NTRI + 255) / 256, 256>>>(scores, mkey, edges, w, denom);
    poolk<<<(2 * NTRI + 7) / 8, 256>>>(cand, w, edges, pooled);

    // output MLP (divide-by-denom fused into A-load)
    gemm_k<2,0,0,true,true><<<dim3(4, gO), blk>>>(pooled, n2_w1, n2_b1, h2, NOBJ, H_, H_,
                                                  nullptr, nullptr, nullptr, denom, nullptr, nullptr);
    gemm_k<0,0,0,true,true><<<dim3(1, gO), blk>>>(h2, n2_w2, n2_b2, out_newobj, NOBJ, DOUT_, H_,
                                                  nullptr, nullptr, nullptr, nullptr, nullptr, nullptr);
}

// round 4
// speedup vs baseline: 1.6784x; 1.5870x over previous
#include <cuda_runtime.h>
#include <cuda_bf16.h>
#include <math.h>
#include <stdint.h>

#define NOBJ 50000
#define NTRI 100000
#define DIN_ 128
#define H_   512
#define DOUT_ 128

// ---------------- scratch (device globals: no allocs allowed) ----------------
static __device__ float    g_h1[(size_t)NTRI * H_];
static __device__ float    g_cand[(size_t)2 * NTRI * H_];
static __device__ float    g_prev[(size_t)NOBJ * H_];
static __device__ float    g_pp[(size_t)NOBJ * H_];
static __device__ float    g_u[(size_t)NOBJ * H_];
static __device__ float    g_z[NOBJ];
static __device__ unsigned g_mkey[NOBJ];
static __device__ float    g_scores[2 * NTRI];
static __device__ float    g_w[2 * NTRI];
static __device__ float    g_denom[NOBJ];
static __device__ float    g_pooled[(size_t)NOBJ * H_];
static __device__ float    g_h2[(size_t)NOBJ * H_];

// 2-term bf16 split weights, [2][N][K] layout (K-major rows, MMA-ready)
static __device__ __nv_bfloat16 g_wproj[2 * 512 * 128];    // proj_w^T
static __device__ __nv_bfloat16 g_wsimT[2 * 512 * 512];    // sim_w^T
static __device__ __nv_bfloat16 g_wsimN[2 * 512 * 512];    // sim_w (direct)
static __device__ __nv_bfloat16 g_wn1a[2 * 512 * 384];     // n1_w1^T
static __device__ __nv_bfloat16 g_wn1b[2 * 1152 * 512];    // n1_w2^T
static __device__ __nv_bfloat16 g_wn2a[2 * 512 * 512];     // n2_w1^T
static __device__ __nv_bfloat16 g_wn2b[2 * 128 * 512];     // n2_w2^T

// ---------------- helpers ----------------
__device__ __forceinline__ void split2(float x, unsigned short& hi, unsigned short& lo) {
    __nv_bfloat16 h = __float2bfloat16_rn(x);
    __nv_bfloat16 l = __float2bfloat16_rn(x - __bfloat162float(h));
    hi = __bfloat16_as_ushort(h);
    lo = __bfloat16_as_ushort(l);
}

__global__ void wsplitT(const float* __restrict__ W, __nv_bfloat16* __restrict__ out,
                        int Kd, int Nd) {
    const int idx = blockIdx.x * blockDim.x + threadIdx.x;
    const size_t NK = (size_t)Nd * Kd;
    if (idx >= (int)NK) return;
    const int n = idx / Kd, k = idx - n * Kd;
    unsigned short a, b;
    split2(W[(size_t)k * Nd + n], a, b);
    out[idx]      = __ushort_as_bfloat16(a);
    out[NK + idx] = __ushort_as_bfloat16(b);
}
__global__ void wsplitN(const float* __restrict__ W, __nv_bfloat16* __restrict__ out,
                        int total) {
    const int idx = blockIdx.x * blockDim.x + threadIdx.x;
    if (idx >= total) return;
    unsigned short a, b;
    split2(W[idx], a, b);
    out[idx]         = __ushort_as_bfloat16(a);
    out[total + idx] = __ushort_as_bfloat16(b);
}

__device__ __forceinline__ void mma16816(float* d, const uint32_t* a, uint32_t b0, uint32_t b1) {
    asm volatile(
        "mma.sync.aligned.m16n8k16.row.col.f32.bf16.bf16.f32 "
        "{%0,%1,%2,%3}, {%4,%5,%6,%7}, {%8,%9}, {%0,%1,%2,%3};"
        : "+f"(d[0]), "+f"(d[1]), "+f"(d[2]), "+f"(d[3])
        : "r"(a[0]), "r"(a[1]), "r"(a[2]), "r"(a[3]), "r"(b0), "r"(b1));
}

// ---------------- HMMA GEMM: D[M,N] = A[M,K] @ Ws^T  (Ws split [2][N][K]) ----------------
// AMODE: 0 plain A[M,K]; 1 gather [obj[s],pred,obj[o]] (K=384); 2 plain scaled by 1/denom[m]
// CMODE: 0 plain C[M,N]; 1 split N=1152 -> cand / out_newp / cand+T
// CTA: 128 thr (2x2 warps), tile 128x128, warp tile 64x64, BK=32.
// smem planes with 80B row pitch (40 halves): conflict-free fragment loads.
#define APITCH 80
#define PLANE  (128 * APITCH)   // 10240 bytes

template<int AMODE, int CMODE, bool RELU, bool HASBIAS>
__global__ __launch_bounds__(128)
void mmak(const float* __restrict__ A, const __nv_bfloat16* __restrict__ Wt,
          const float* __restrict__ bias, float* __restrict__ C,
          int M, int N, int K,
          const float* __restrict__ obj, const float* __restrict__ pred,
          const int* __restrict__ edges, const float* __restrict__ denomv,
          float* __restrict__ outp, float* __restrict__ candp)
{
    __shared__ __align__(16) unsigned char sm[4 * PLANE];
    unsigned char* const smA0 = sm;
    unsigned char* const smA1 = sm + PLANE;
    unsigned char* const smB0 = sm + 2 * PLANE;
    unsigned char* const smB1 = sm + 3 * PLANE;

    const int tid  = threadIdx.x;
    const int lane = tid & 31, wid = tid >> 5;
    const int wr = wid >> 1, wc = wid & 1;
    const int bm = blockIdx.y * 128, bn = blockIdx.x * 128;
    const size_t NK = (size_t)N * K;

    float acc[4][8][4];
    #pragma unroll
    for (int i = 0; i < 4; i++)
        #pragma unroll
        for (int j = 0; j < 8; j++)
            #pragma unroll
            for (int q = 0; q < 4; q++) acc[i][j][q] = 0.f;

    const int arow = lane >> 2;
    const int acol = (lane & 3) * 2;

    const int nch = K >> 5;
    for (int ch = 0; ch < nch; ch++) {
        const int k0 = ch << 5;

        // ---- stage A: 128 rows x 32 k fp32 -> split -> 2 planes ----
        #pragma unroll
        for (int it = 0; it < 8; it++) {
            const int idx = (it << 7) + tid;
            const int m = idx >> 3, q = idx & 7;
            const int gm = bm + m;
            float4 v = make_float4(0.f, 0.f, 0.f, 0.f);
            if (gm < M) {
                const int kk = k0 + (q << 2);
                const float* p;
                if (AMODE == 1) {
                    if (kk < DIN_)          p = obj  + (size_t)edges[2 * gm] * DIN_ + kk;
                    else if (kk < 2 * DIN_) p = pred + (size_t)gm * DIN_ + (kk - DIN_);
                    else                    p = obj  + (size_t)edges[2 * gm + 1] * DIN_ + (kk - 2 * DIN_);
                } else {
                    p = A + (size_t)gm * K + kk;
                }
                v = *(const float4*)p;
                if (AMODE == 2) {
                    const float sc = __fdividef(1.f, denomv[gm]);
                    v.x *= sc; v.y *= sc; v.z *= sc; v.w *= sc;
                }
            }
            unsigned short h[4], l[4];
            split2(v.x, h[0], l[0]); split2(v.y, h[1], l[1]);
            split2(v.z, h[2], l[2]); split2(v.w, h[3], l[3]);
            const int boff = m * APITCH + (q << 3);
            *(uint2*)(smA0 + boff) = make_uint2((uint32_t)h[0] | ((uint32_t)h[1] << 16),
                                                (uint32_t)h[2] | ((uint32_t)h[3] << 16));
            *(uint2*)(smA1 + boff) = make_uint2((uint32_t)l[0] | ((uint32_t)l[1] << 16),
                                                (uint32_t)l[2] | ((uint32_t)l[3] << 16));
        }

        // ---- stage B: 2 planes, 128 n-rows x 32 k bf16 ----
        #pragma unroll
        for (int p = 0; p < 2; p++) {
            const __nv_bfloat16* Wp = Wt + (size_t)p * NK;
            unsigned char* dstp = p ? smB1 : smB0;
            #pragma unroll
            for (int it = 0; it < 4; it++) {
                const int idx = (it << 7) + tid;
                const int n = idx >> 2, seg = idx & 3;
                const uint4 vv = *(const uint4*)(Wp + (size_t)(bn + n) * K + k0 + (seg << 3));
                *(uint4*)(dstp + n * APITCH + (seg << 4)) = vv;
            }
        }
        __syncthreads();

        // ---- MMA: 2 k16-steps ----
        #pragma unroll
        for (int s = 0; s < 2; s++) {
            const int ks = s << 4;
            uint32_t af[2][4][4];
            #pragma unroll
            for (int i = 0; i < 4; i++) {
                const int r = wr * 64 + i * 16 + arow;
                const int b0 = r * APITCH + (ks + acol) * 2;
                af[0][i][0] = *(const uint32_t*)(smA0 + b0);
                af[0][i][1] = *(const uint32_t*)(smA0 + b0 + 8 * APITCH);
                af[0][i][2] = *(const uint32_t*)(smA0 + b0 + 16);
                af[0][i][3] = *(const uint32_t*)(smA0 + b0 + 8 * APITCH + 16);
                af[1][i][0] = *(const uint32_t*)(smA1 + b0);
                af[1][i][1] = *(const uint32_t*)(smA1 + b0 + 8 * APITCH);
                af[1][i][2] = *(const uint32_t*)(smA1 + b0 + 16);
                af[1][i][3] = *(const uint32_t*)(smA1 + b0 + 8 * APITCH + 16);
            }
            #pragma unroll
            for (int j = 0; j < 8; j++) {
                const int n = wc * 64 + j * 8 + arow;
                const int b0 = n * APITCH + (ks + acol) * 2;
                const uint32_t bh0 = *(const uint32_t*)(smB0 + b0);
                const uint32_t bh1 = *(const uint32_t*)(smB0 + b0 + 16);
                const uint32_t bl0 = *(const uint32_t*)(smB1 + b0);
                const uint32_t bl1 = *(const uint32_t*)(smB1 + b0 + 16);
                #pragma unroll
                for (int i = 0; i < 4; i++) {
                    mma16816(acc[i][j], af[0][i], bh0, bh1);  // hi*hi
                    mma16816(acc[i][j], af[0][i], bl0, bl1);  // hi*lo
                    mma16816(acc[i][j], af[1][i], bh0, bh1);  // lo*hi
                }
            }
        }
        __syncthreads();
    }

    // ---- epilogue ----
    #pragma unroll
    for (int i = 0; i < 4; i++) {
        #pragma unroll
        for (int j = 0; j < 8; j++) {
            const int gm0 = bm + wr * 64 + i * 16 + arow;
            const int gn  = bn + wc * 64 + j * 8 + acol;
            float2 bb = make_float2(0.f, 0.f);
            if (HASBIAS) bb = *(const float2*)&bias[gn];
            #pragma unroll
            for (int h = 0; h < 2; h++) {
                const int m = gm0 + h * 8;
                if (m < M) {
                    float x0 = acc[i][j][2 * h]     + bb.x;
                    float x1 = acc[i][j][2 * h + 1] + bb.y;
                    if (RELU) { x0 = fmaxf(x0, 0.f); x1 = fmaxf(x1, 0.f); }
                    float* dst;
                    if (CMODE == 0) {
                        dst = C + (size_t)m * N + gn;
                    } else {
                        if (gn < H_)              dst = candp + (size_t)m * H_ + gn;
                        else if (gn < H_ + DOUT_) dst = outp + (size_t)m * DOUT_ + (gn - H_);
                        else                      dst = candp + (size_t)(NTRI + m) * H_ + (gn - H_ - DOUT_);
                    }
                    *(float2*)dst = make_float2(x0, x1);
                }
            }
        }
    }
}

// ---------------- softmax / pooling kernels ----------------
__device__ __forceinline__ unsigned fenc(float f) {
    unsigned u = __float_as_uint(f);
    return (u & 0x80000000u) ? ~u : (u | 0x80000000u);
}
__device__ __forceinline__ float fdec(unsigned e) {
    unsigned u = (e & 0x80000000u) ? (e & 0x7fffffffu) : ~e;
    return __uint_as_float(u);
}

__global__ void zk(const float* __restrict__ pp, const float* __restrict__ simb,
                   float* __restrict__ z, unsigned* __restrict__ mkey)
{
    const int warp = (blockIdx.x * blockDim.x + threadIdx.x) >> 5;
    const int lane = threadIdx.x & 31;
    if (warp >= NOBJ) return;
    const float4* a = (const float4*)(pp + (size_t)warp * H_);
    const float4* b = (const float4*)simb;
    float s = 0.f;
    #pragma unroll
    for (int q = 0; q < 4; q++) {
        float4 x = a[lane + q * 32], y = b[lane + q * 32];
        s += x.x * y.x + x.y * y.y + x.z * y.z + x.w * y.w;
    }
    #pragma unroll
    for (int o = 16; o; o >>= 1) s += __shfl_down_sync(0xffffffffu, s, o);
    if (lane == 0) { z[warp] = s; mkey[warp] = fenc(s); }
}

__global__ void scorek(const float* __restrict__ cand, const float* __restrict__ u,
                       const float* __restrict__ z, const int* __restrict__ edges,
                       float* __restrict__ scores, unsigned* __restrict__ mkey)
{
    const int e = (blockIdx.x * blockDim.x + threadIdx.x) >> 5;
    const int lane = threadIdx.x & 31;
    if (e >= 2 * NTRI) return;
    const int idx = (e < NTRI) ? edges[2 * e] : edges[2 * (e - NTRI) + 1];
    const float4* a = (const float4*)(cand + (size_t)e * H_);
    const float4* b = (const float4*)(u + (size_t)idx * H_);
    float s = 0.f;
    #pragma unroll
    for (int q = 0; q < 4; q++) {
        float4 x = a[lane + q * 32], y = b[lane + q * 32];
        s += x.x * y.x + x.y * y.y + x.z * y.z + x.w * y.w;
    }
    #pragma unroll
    for (int o = 16; o; o >>= 1) s += __shfl_down_sync(0xffffffffu, s, o);
    if (lane == 0) {
        const float sc = s + z[idx];
        scores[e] = sc;
        atomicMax(mkey + idx, fenc(sc));
    }
}

__global__ void zerok(float* __restrict__ p, size_t n)
{
    size_t i = (size_t)blockIdx.x * blockDim.x + threadIdx.x;
    const size_t stride = (size_t)gridDim.x * blockDim.x;
    for (; i < n; i += stride) p[i] = 0.f;
}

__global__ void dinitk(const float* __restrict__ z, const unsigned* __restrict__ mkey,
                       float* __restrict__ denom)
{
    const int i = blockIdx.x * blockDim.x + threadIdx.x;
    if (i < NOBJ) denom[i] = expf(z[i] - fdec(mkey[i]));
}

__global__ void wk(const float* __restrict__ scores, const unsigned* __restrict__ mkey,
                   const int* __restrict__ edges, float* __restrict__ w,
                   float* __restrict__ denom)
{
    const int e = blockIdx.x * blockDim.x + threadIdx.x;
    if (e >= 2 * NTRI) return;
    const int idx = (e < NTRI) ? edges[2 * e] : edges[2 * (e - NTRI) + 1];
    const float ww = expf(scores[e] - fdec(mkey[idx]));
    w[e] = ww;
    atomicAdd(denom + idx, ww);
}

__global__ void poolk(const float* __restrict__ cand, const float* __restrict__ w,
                      const int* __restrict__ edges, float* __restrict__ pooled)
{
    const int e = (blockIdx.x * blockDim.x + threadIdx.x) >> 5;
    const int lane = threadIdx.x & 31;
    if (e >= 2 * NTRI) return;
    const int idx = (e < NTRI) ? edges[2 * e] : edges[2 * (e - NTRI) + 1];
    const float ww = w[e];
    const float4* src = (const float4*)(cand + (size_t)e * H_);
    float* dst = pooled + (size_t)idx * H_;
    #pragma unroll
    for (int q = 0; q < 4; q++) {
        float4 v = src[lane + q * 32];
        float* d = dst + (size_t)(lane + q * 32) * 4;
        asm volatile("red.global.add.v4.f32 [%0], {%1, %2, %3, %4};"
                     :: "l"(d), "f"(v.x * ww), "f"(v.y * ww), "f"(v.z * ww), "f"(v.w * ww)
                     : "memory");
    }
}

extern "C" void kernel_launch(void* const* d_in, const int* in_sizes, int n_in,
                              void* d_out, int out_size)
{
    const float* obj    = (const float*)d_in[0];
    const float* pred   = (const float*)d_in[1];
    const int*   edges  = (const int*)d_in[2];
    const float* n1_w1  = (const float*)d_in[3];
    const float* n1_b1  = (const float*)d_in[4];
    const float* n1_w2  = (const float*)d_in[5];
    const float* n1_b2  = (const float*)d_in[6];
    const float* n2_w1  = (const float*)d_in[7];
    const float* n2_b1  = (const float*)d_in[8];
    const float* n2_w2  = (const float*)d_in[9];
    const float* n2_b2  = (const float*)d_in[10];
    const float* proj_w = (const float*)d_in[11];
    const float* proj_b = (const float*)d_in[12];
    const float* sim_w  = (const float*)d_in[13];
    const float* sim_b  = (const float*)d_in[14];

    float* out        = (float*)d_out;
    float* out_newobj = out;
    float* out_newp   = out + (size_t)NOBJ * DOUT_;

    float *h1, *cand, *prev, *pp, *u, *z, *scores, *w, *denom, *pooled, *h2;
    unsigned* mkey;
    __nv_bfloat16 *wproj, *wsimT, *wsimN, *wn1a, *wn1b, *wn2a, *wn2b;
    cudaGetSymbolAddress((void**)&h1, g_h1);
    cudaGetSymbolAddress((void**)&cand, g_cand);
    cudaGetSymbolAddress((void**)&prev, g_prev);
    cudaGetSymbolAddress((void**)&pp, g_pp);
    cudaGetSymbolAddress((void**)&u, g_u);
    cudaGetSymbolAddress((void**)&z, g_z);
    cudaGetSymbolAddress((void**)&mkey, g_mkey);
    cudaGetSymbolAddress((void**)&scores, g_scores);
    cudaGetSymbolAddress((void**)&w, g_w);
    cudaGetSymbolAddress((void**)&denom, g_denom);
    cudaGetSymbolAddress((void**)&pooled, g_pooled);
    cudaGetSymbolAddress((void**)&h2, g_h2);
    cudaGetSymbolAddress((void**)&wproj, g_wproj);
    cudaGetSymbolAddress((void**)&wsimT, g_wsimT);
    cudaGetSymbolAddress((void**)&wsimN, g_wsimN);
    cudaGetSymbolAddress((void**)&wn1a, g_wn1a);
    cudaGetSymbolAddress((void**)&wn1b, g_wn1b);
    cudaGetSymbolAddress((void**)&wn2a, g_wn2a);
    cudaGetSymbolAddress((void**)&wn2b, g_wn2b);

    const int gO = (NOBJ + 127) / 128;   // 391
    const int gT = (NTRI + 127) / 128;   // 782
    const dim3 blk(128);

    // weight split/transpose (tiny)
    wsplitT<<<(512 * 128 + 255) / 256, 256>>>(proj_w, wproj, 128, 512);
    wsplitT<<<(512 * 512 + 255) / 256, 256>>>(sim_w, wsimT, 512, 512);
    wsplitN<<<(512 * 512 + 255) / 256, 256>>>(sim_w, wsimN, 512 * 512);
    wsplitT<<<(512 * 384 + 255) / 256, 256>>>(n1_w1, wn1a, 384, 512);
    wsplitT<<<(1152 * 512 + 255) / 256, 256>>>(n1_w2, wn1b, 512, 1152);
    wsplitT<<<(512 * 512 + 255) / 256, 256>>>(n2_w1, wn2a, 512, 512);
    wsplitT<<<(512 * 128 + 255) / 256, 256>>>(n2_w2, wn2b, 512, 128);

    // object-side projections
    mmak<0,0,false,true><<<dim3(4, gO), blk>>>(obj, wproj, proj_b, prev, NOBJ, 512, 128,
                                               nullptr, nullptr, nullptr, nullptr, nullptr, nullptr);
    mmak<0,0,false,true><<<dim3(4, gO), blk>>>(prev, wsimT, sim_b, pp, NOBJ, 512, 512,
                                               nullptr, nullptr, nullptr, nullptr, nullptr, nullptr);
    mmak<0,0,false,false><<<dim3(4, gO), blk>>>(pp, wsimN, nullptr, u, NOBJ, 512, 512,
                                                nullptr, nullptr, nullptr, nullptr, nullptr, nullptr);
    zk<<<(NOBJ * 32 + 255) / 256, 256>>>(pp, sim_b, z, mkey);

    // triple MLP (gather fused; outputs split into cand / new_p)
    mmak<1,0,true,true><<<dim3(4, gT), blk>>>(nullptr, wn1a, n1_b1, h1, NTRI, 512, 384,
                                              obj, pred, edges, nullptr, nullptr, nullptr);
    mmak<0,1,true,true><<<dim3(9, gT), blk>>>(h1, wn1b, n1_b2, nullptr, NTRI, 1152, 512,
                                              nullptr, nullptr, nullptr, nullptr, out_newp, cand);

    // attention scores + segment softmax
    scorek<<<(2 * NTRI + 7) / 8, 256>>>(cand, u, z, edges, scores, mkey);
    zerok<<<2048, 256>>>(pooled, (size_t)NOBJ * H_);
    dinitk<<<(NOBJ + 255) / 256, 256>>>(z, mkey, denom);
    wk<<<(2 * NTRI + 255) / 256, 256>>>(scores, mkey, edges, w, denom);
    poolk<<<(2 * NTRI + 7) / 8, 256>>>(cand, w, edges, pooled);

    // output MLP (divide-by-denom fused)
    mmak<2,0,true,true><<<dim3(4, gO), blk>>>(pooled, wn2a, n2_b1, h2, NOBJ, 512, 512,
                                              nullptr, nullptr, nullptr, denom, nullptr, nullptr);
    mmak<0,0,true,true><<<dim3(1, gO), blk>>>(h2, wn2b, n2_b2, out_newobj, NOBJ, 128, 512,
                                              nullptr, nullptr, nullptr, nullptr, nullptr, nullptr);
}

// round 5
// speedup vs baseline: 1.9566x; 1.1658x over previous
#include <cuda_runtime.h>
#include <cuda_bf16.h>
#include <math.h>
#include <stdint.h>

#define NOBJ 50000
#define NTRI 100000
#define DIN_ 128
#define H_   512
#define DOUT_ 128

// ---------------- scratch (device globals: no allocs allowed) ----------------
static __device__ float    g_cand[(size_t)2 * NTRI * H_];   // fp32 (scorek/poolk)
static __device__ float    g_pooled[(size_t)NOBJ * H_];
static __device__ float    g_z[NOBJ];
static __device__ unsigned g_mkey[NOBJ];
static __device__ float    g_scores[2 * NTRI];
static __device__ float    g_w[2 * NTRI];
static __device__ float    g_denom[NOBJ];

// 2-term bf16 split planes [2][M][K]
static __device__ __nv_bfloat16 g_objs [(size_t)2 * NOBJ * DIN_];
static __device__ __nv_bfloat16 g_preds[(size_t)2 * NTRI * DIN_];
static __device__ __nv_bfloat16 g_h1s  [(size_t)2 * NTRI * H_];
static __device__ __nv_bfloat16 g_prevs[(size_t)2 * NOBJ * H_];
static __device__ __nv_bfloat16 g_pps  [(size_t)2 * NOBJ * H_];
static __device__ __nv_bfloat16 g_us   [(size_t)2 * NOBJ * H_];
static __device__ __nv_bfloat16 g_h2s  [(size_t)2 * NOBJ * H_];

// 2-term bf16 split weights, [2][N][K]
static __device__ __nv_bfloat16 g_wproj[2 * 512 * 128];
static __device__ __nv_bfloat16 g_wsimT[2 * 512 * 512];
static __device__ __nv_bfloat16 g_wsimN[2 * 512 * 512];
static __device__ __nv_bfloat16 g_wn1a[2 * 512 * 384];
static __device__ __nv_bfloat16 g_wn1b[2 * 1152 * 512];
static __device__ __nv_bfloat16 g_wn2a[2 * 512 * 512];
static __device__ __nv_bfloat16 g_wn2b[2 * 128 * 512];

// ---------------- helpers ----------------
__device__ __forceinline__ void split2(float x, unsigned short& hi, unsigned short& lo) {
    __nv_bfloat16 h = __float2bfloat16_rn(x);
    __nv_bfloat16 l = __float2bfloat16_rn(x - __bfloat162float(h));
    hi = __bfloat16_as_ushort(h);
    lo = __bfloat16_as_ushort(l);
}
__device__ __forceinline__ float2 bf2(uint32_t u) {
    return make_float2(__bfloat162float(__ushort_as_bfloat16((unsigned short)(u & 0xffff))),
                       __bfloat162float(__ushort_as_bfloat16((unsigned short)(u >> 16))));
}
__device__ __forceinline__ uint32_t smem_u32(const void* p) {
    uint32_t a;
    asm("{ .reg .u64 t; cvta.to.shared.u64 t, %1; cvt.u32.u64 %0, t; }" : "=r"(a) : "l"(p));
    return a;
}
__device__ __forceinline__ void cpa16(uint32_t dst, const void* src, uint32_t sz) {
    asm volatile("cp.async.cg.shared.global [%0], [%1], 16, %2;"
                 :: "r"(dst), "l"(src), "r"(sz) : "memory");
}
#define CPA_COMMIT() asm volatile("cp.async.commit_group;" ::: "memory")
#define CPA_WAIT0()  asm volatile("cp.async.wait_group 0;" ::: "memory")

__device__ __forceinline__ void mma16816(float* d, const uint32_t* a, uint32_t b0, uint32_t b1) {
    asm volatile(
        "mma.sync.aligned.m16n8k16.row.col.f32.bf16.bf16.f32 "
        "{%0,%1,%2,%3}, {%4,%5,%6,%7}, {%8,%9}, {%0,%1,%2,%3};"
        : "+f"(d[0]), "+f"(d[1]), "+f"(d[2]), "+f"(d[3])
        : "r"(a[0]), "r"(a[1]), "r"(a[2]), "r"(a[3]), "r"(b0), "r"(b1));
}

// weight split kernels: out[2][Nd][Kd]
__global__ void wsplitT(const float* __restrict__ W, __nv_bfloat16* __restrict__ out,
                        int Kd, int Nd) {
    const int idx = blockIdx.x * blockDim.x + threadIdx.x;
    const size_t NK = (size_t)Nd * Kd;
    if (idx >= (int)NK) return;
    const int n = idx / Kd, k = idx - n * Kd;
    unsigned short a, b;
    split2(W[(size_t)k * Nd + n], a, b);
    out[idx]      = __ushort_as_bfloat16(a);
    out[NK + idx] = __ushort_as_bfloat16(b);
}
__global__ void wsplitN(const float* __restrict__ W, __nv_bfloat16* __restrict__ out,
                        int total) {
    const int idx = blockIdx.x * blockDim.x + threadIdx.x;
    if (idx >= total) return;
    unsigned short a, b;
    split2(W[idx], a, b);
    out[idx]         = __ushort_as_bfloat16(a);
    out[total + idx] = __ushort_as_bfloat16(b);
}
// input split: dst[2][n]
__global__ void isplit(const float* __restrict__ src, __nv_bfloat16* __restrict__ dst, int n) {
    const int i = blockIdx.x * blockDim.x + threadIdx.x;
    if (i >= n) return;
    unsigned short a, b;
    split2(src[i], a, b);
    dst[i]     = __ushort_as_bfloat16(a);
    dst[n + i] = __ushort_as_bfloat16(b);
}

// ---------------- HMMA GEMM: D[M,N] = A[M,K] @ Ws^T ----------------
// AMODE: 0 A = split planes As[2][M][K]; 1 gather split [objs|preds|objs] (K=384);
//        2 A = fp32 Af scaled by 1/denom[m] (runtime split)
// OMODE: 0 fp32 C; 1 split planes Cs[2][M][N]; 2 split N=1152 -> cand / out_newp / cand+T (fp32)
// 256 thr (2x4 warps), CTA tile 128x128, warp tile 64x32, BK=32, double-buffered cp.async.
#define APITCH 80
#define PLANE  (128 * APITCH)                 // 10240 B
#define SMEMB  (8 * PLANE)                    // 81920 B

template<int AMODE, int OMODE, bool RELU, bool HASBIAS>
__global__ __launch_bounds__(256)
void mmak(const __nv_bfloat16* __restrict__ As, const float* __restrict__ Af,
          const __nv_bfloat16* __restrict__ Wt,
          const float* __restrict__ bias, float* __restrict__ Cf,
          __nv_bfloat16* __restrict__ Cs,
          int M, int N, int K,
          const __nv_bfloat16* __restrict__ objs, const __nv_bfloat16* __restrict__ preds,
          const int* __restrict__ edges, const float* __restrict__ denomv,
          float* __restrict__ outp, float* __restrict__ candp)
{
    extern __shared__ __align__(16) unsigned char sm[];
    const int tid = threadIdx.x;
    const int lane = tid & 31, wid = tid >> 5;
    const int wr = wid >> 2, wc = wid & 3;
    const int bm = blockIdx.y * 128, bn = blockIdx.x * 128;
    const size_t MK = (size_t)M * K, NK = (size_t)N * K, MN = (size_t)M * N;
    const uint32_t sb = smem_u32(sm);
    const int arow = lane >> 2, acol = (lane & 3) << 1;

    float acc[4][4][4];
    #pragma unroll
    for (int i = 0; i < 4; i++)
        #pragma unroll
        for (int j = 0; j < 4; j++)
            #pragma unroll
            for (int q = 0; q < 4; q++) acc[i][j][q] = 0.f;

    float4 pf[4];  // AMODE2 prefetch

    auto stageAsync = [&](int k0, int b) {
        const uint32_t smA = sb + b * 4 * PLANE;
        const uint32_t smB = smA + 2 * PLANE;
        if (AMODE == 0) {
            #pragma unroll
            for (int it = 0; it < 4; it++) {
                const int idx = (it << 8) + tid;
                const int p = idx >> 9, r = (idx >> 2) & 127, seg = idx & 3;
                const int gm = bm + r;
                const int gmc = gm < M ? gm : M - 1;
                const __nv_bfloat16* src = As + (size_t)p * MK + (size_t)gmc * K + k0 + seg * 8;
                cpa16(smA + p * PLANE + r * APITCH + seg * 16, src, gm < M ? 16u : 0u);
            }
        } else if (AMODE == 1) {
            #pragma unroll
            for (int it = 0; it < 4; it++) {
                const int idx = (it << 8) + tid;
                const int p = idx >> 9, r = (idx >> 2) & 127, seg = idx & 3;
                const int gm = bm + r;
                const int gmc = gm < M ? gm : M - 1;
                const __nv_bfloat16* src;
                if (k0 < DIN_)
                    src = objs + (size_t)p * ((size_t)NOBJ * DIN_)
                        + (size_t)edges[2 * gmc] * DIN_ + k0 + seg * 8;
                else if (k0 < 2 * DIN_)
                    src = preds + (size_t)p * ((size_t)NTRI * DIN_)
                        + (size_t)gmc * DIN_ + (k0 - DIN_) + seg * 8;
                else
                    src = objs + (size_t)p * ((size_t)NOBJ * DIN_)
                        + (size_t)edges[2 * gmc + 1] * DIN_ + (k0 - 2 * DIN_) + seg * 8;
                cpa16(smA + p * PLANE + r * APITCH + seg * 16, src, gm < M ? 16u : 0u);
            }
        }
        #pragma unroll
        for (int it = 0; it < 4; it++) {
            const int idx = (it << 8) + tid;
            const int p = idx >> 9, n = (idx >> 2) & 127, seg = idx & 3;
            const __nv_bfloat16* src = Wt + (size_t)p * NK + (size_t)(bn + n) * K + k0 + seg * 8;
            cpa16(smB + p * PLANE + n * APITCH + seg * 16, src, 16u);
        }
        CPA_COMMIT();
    };

    auto loadA2 = [&](int k0) {
        #pragma unroll
        for (int it = 0; it < 4; it++) {
            const int idx = (it << 8) + tid;
            const int m = idx >> 3, q = idx & 7;
            const int gm = bm + m;
            float4 v = make_float4(0.f, 0.f, 0.f, 0.f);
            if (gm < M) {
                v = *(const float4*)(Af + (size_t)gm * K + k0 + (q << 2));
                const float sc = __fdividef(1.f, denomv[gm]);
                v.x *= sc; v.y *= sc; v.z *= sc; v.w *= sc;
            }
            pf[it] = v;
        }
    };
    auto stsA2 = [&](int b) {
        unsigned char* smA = sm + b * 4 * PLANE;
        #pragma unroll
        for (int it = 0; it < 4; it++) {
            const int idx = (it << 8) + tid;
            const int m = idx >> 3, q = idx & 7;
            unsigned short h[4], l[4];
            split2(pf[it].x, h[0], l[0]); split2(pf[it].y, h[1], l[1]);
            split2(pf[it].z, h[2], l[2]); split2(pf[it].w, h[3], l[3]);
            const int boff = m * APITCH + (q << 3);
            *(uint2*)(smA + boff) = make_uint2((uint32_t)h[0] | ((uint32_t)h[1] << 16),
                                               (uint32_t)h[2] | ((uint32_t)h[3] << 16));
            *(uint2*)(smA + PLANE + boff) = make_uint2((uint32_t)l[0] | ((uint32_t)l[1] << 16),
                                                       (uint32_t)l[2] | ((uint32_t)l[3] << 16));
        }
    };

    auto compute = [&](int b) {
        const unsigned char* a0 = sm + b * 4 * PLANE;
        const unsigned char* a1 = a0 + PLANE;
        const unsigned char* bb0 = a0 + 2 * PLANE;
        const unsigned char* bb1 = a0 + 3 * PLANE;
        #pragma unroll
        for (int s = 0; s < 2; s++) {
            const int ks = s << 4;
            uint32_t af[2][4][4];
            #pragma unroll
            for (int i = 0; i < 4; i++) {
                const int r = wr * 64 + i * 16 + arow;
                const int off = r * APITCH + (ks + acol) * 2;
                af[0][i][0] = *(const uint32_t*)(a0 + off);
                af[0][i][1] = *(const uint32_t*)(a0 + off + 8 * APITCH);
                af[0][i][2] = *(const uint32_t*)(a0 + off + 16);
                af[0][i][3] = *(const uint32_t*)(a0 + off + 8 * APITCH + 16);
                af[1][i][0] = *(const uint32_t*)(a1 + off);
                af[1][i][1] = *(const uint32_t*)(a1 + off + 8 * APITCH);
                af[1][i][2] = *(const uint32_t*)(a1 + off + 16);
                af[1][i][3] = *(const uint32_t*)(a1 + off + 8 * APITCH + 16);
            }
            uint32_t bh[4][2], bl[4][2];
            #pragma unroll
            for (int j = 0; j < 4; j++) {
                const int n = wc * 32 + j * 8 + arow;
                const int off = n * APITCH + (ks + acol) * 2;
                bh[j][0] = *(const uint32_t*)(bb0 + off);
                bh[j][1] = *(const uint32_t*)(bb0 + off + 16);
                bl[j][0] = *(const uint32_t*)(bb1 + off);
                bl[j][1] = *(const uint32_t*)(bb1 + off + 16);
            }
            // product-major ordering: 16 independent accumulators between reuses
            #pragma unroll
            for (int j = 0; j < 4; j++)
                #pragma unroll
                for (int i = 0; i < 4; i++)
                    mma16816(acc[i][j], af[0][i], bh[j][0], bh[j][1]);
            #pragma unroll
            for (int j = 0; j < 4; j++)
                #pragma unroll
                for (int i = 0; i < 4; i++)
                    mma16816(acc[i][j], af[1][i], bh[j][0], bh[j][1]);
            #pragma unroll
            for (int j = 0; j < 4; j++)
                #pragma unroll
                for (int i = 0; i < 4; i++)
                    mma16816(acc[i][j], af[0][i], bl[j][0], bl[j][1]);
        }
    };

    const int nch = K >> 5;
    stageAsync(0, 0);
    if (AMODE == 2) { loadA2(0); stsA2(0); }
    CPA_WAIT0();
    __syncthreads();

    for (int ch = 0; ch < nch; ch++) {
        const int b = ch & 1;
        const bool nxt = (ch + 1) < nch;
        if (nxt) {
            stageAsync((ch + 1) << 5, b ^ 1);
            if (AMODE == 2) loadA2((ch + 1) << 5);
        }
        compute(b);
        if (nxt && AMODE == 2) stsA2(b ^ 1);
        CPA_WAIT0();
        __syncthreads();
    }

    // ---- epilogue ----
    #pragma unroll
    for (int i = 0; i < 4; i++)
        #pragma unroll
        for (int j = 0; j < 4; j++) {
            const int gm0 = bm + wr * 64 + i * 16 + arow;
            const int gn  = bn + wc * 32 + j * 8 + acol;
            float2 bb = make_float2(0.f, 0.f);
            if (HASBIAS) bb = *(const float2*)&bias[gn];
            #pragma unroll
            for (int h = 0; h < 2; h++) {
                const int m = gm0 + h * 8;
                if (m < M) {
                    float x0 = acc[i][j][2 * h]     + bb.x;
                    float x1 = acc[i][j][2 * h + 1] + bb.y;
                    if (RELU) { x0 = fmaxf(x0, 0.f); x1 = fmaxf(x1, 0.f); }
                    if (OMODE == 0) {
                        *(float2*)(Cf + (size_t)m * N + gn) = make_float2(x0, x1);
                    } else if (OMODE == 1) {
                        unsigned short h0, l0, h1, l1;
                        split2(x0, h0, l0); split2(x1, h1, l1);
                        *(uint32_t*)(Cs + (size_t)m * N + gn)      = (uint32_t)h0 | ((uint32_t)h1 << 16);
                        *(uint32_t*)(Cs + MN + (size_t)m * N + gn) = (uint32_t)l0 | ((uint32_t)l1 << 16);
                    } else {
                        float* dst;
                        if (gn < H_)              dst = candp + (size_t)m * H_ + gn;
                        else if (gn < H_ + DOUT_) dst = outp + (size_t)m * DOUT_ + (gn - H_);
                        else                      dst = candp + (size_t)(NTRI + m) * H_ + (gn - H_ - DOUT_);
                        *(float2*)dst = make_float2(x0, x1);
                    }
                }
            }
        }
}

// ---------------- softmax / pooling kernels ----------------
__device__ __forceinline__ unsigned fenc(float f) {
    unsigned u = __float_as_uint(f);
    return (u & 0x80000000u) ? ~u : (u | 0x80000000u);
}
__device__ __forceinline__ float fdec(unsigned e) {
    unsigned u = (e & 0x80000000u) ? (e & 0x7fffffffu) : ~e;
    return __uint_as_float(u);
}

// z[i] = (pps_hi[i]+pps_lo[i]) . sim_b ; seed mkey
__global__ void zk2(const __nv_bfloat16* __restrict__ pps, const float* __restrict__ simb,
                    float* __restrict__ z, unsigned* __restrict__ mkey)
{
    const int row = (blockIdx.x * blockDim.x + threadIdx.x) >> 5;
    const int lane = threadIdx.x & 31;
    if (row >= NOBJ) return;
    const size_t PS = (size_t)NOBJ * H_;
    const uint2* ph = (const uint2*)(pps + (size_t)row * H_);
    const uint2* pl = (const uint2*)(pps + PS + (size_t)row * H_);
    float s = 0.f;
    #pragma unroll
    for (int q = 0; q < 4; q++) {
        const int t = lane + q * 32;
        uint2 a = ph[t], b = pl[t];
        float4 w4 = *(const float4*)&simb[t * 4];
        float2 a0 = bf2(a.x), a1 = bf2(a.y), b0 = bf2(b.x), b1 = bf2(b.y);
        s += (a0.x + b0.x) * w4.x + (a0.y + b0.y) * w4.y
           + (a1.x + b1.x) * w4.z + (a1.y + b1.y) * w4.w;
    }
    #pragma unroll
    for (int o = 16; o; o >>= 1) s += __shfl_down_sync(0xffffffffu, s, o);
    if (lane == 0) { z[row] = s; mkey[row] = fenc(s); }
}

// scores[e] = cand[e] . (us_hi+us_lo)[idx] + z[idx];  atomicMax into mkey
__global__ void scorek2(const float* __restrict__ cand, const __nv_bfloat16* __restrict__ us,
                        const float* __restrict__ z, const int* __restrict__ edges,
                        float* __restrict__ scores, unsigned* __restrict__ mkey)
{
    const int e = (blockIdx.x * blockDim.x + threadIdx.x) >> 5;
    const int lane = threadIdx.x & 31;
    if (e >= 2 * NTRI) return;
    const int idx = (e < NTRI) ? edges[2 * e] : edges[2 * (e - NTRI) + 1];
    const size_t PS = (size_t)NOBJ * H_;
    const float4* a = (const float4*)(cand + (size_t)e * H_);
    const uint2* uh = (const uint2*)(us + (size_t)idx * H_);
    const uint2* ul = (const uint2*)(us + PS + (size_t)idx * H_);
    float s = 0.f;
    #pragma unroll
    for (int q = 0; q < 4; q++) {
        const int t = lane + q * 32;
        float4 x = a[t];
        uint2 hu = uh[t], lu = ul[t];
        float2 h0 = bf2(hu.x), h1 = bf2(hu.y), l0 = bf2(lu.x), l1 = bf2(lu.y);
        s += x.x * (h0.x + l0.x) + x.y * (h0.y + l0.y)
           + x.z * (h1.x + l1.x) + x.w * (h1.y + l1.y);
    }
    #pragma unroll
    for (int o = 16; o; o >>= 1) s += __shfl_down_sync(0xffffffffu, s, o);
    if (lane == 0) {
        const float sc = s + z[idx];
        scores[e] = sc;
        atomicMax(mkey + idx, fenc(sc));
    }
}

__global__ void zerok(float* __restrict__ p, size_t n)
{
    size_t i = (size_t)blockIdx.x * blockDim.x + threadIdx.x;
    const size_t stride = (size_t)gridDim.x * blockDim.x;
    for (; i < n; i += stride) p[i] = 0.f;
}

__global__ void dinitk(const float* __restrict__ z, const unsigned* __restrict__ mkey,
                       float* __restrict__ denom)
{
    const int i = blockIdx.x * blockDim.x + threadIdx.x;
    if (i < NOBJ) denom[i] = expf(z[i] - fdec(mkey[i]));
}

__global__ void wk(const float* __restrict__ scores, const unsigned* __restrict__ mkey,
                   const int* __restrict__ edges, float* __restrict__ w,
                   float* __restrict__ denom)
{
    const int e = blockIdx.x * blockDim.x + threadIdx.x;
    if (e >= 2 * NTRI) return;
    const int idx = (e < NTRI) ? edges[2 * e] : edges[2 * (e - NTRI) + 1];
    const float ww = expf(scores[e] - fdec(mkey[idx]));
    w[e] = ww;
    atomicAdd(denom + idx, ww);
}

__global__ void poolk(const float* __restrict__ cand, const float* __restrict__ w,
                      const int* __restrict__ edges, float* __restrict__ pooled)
{
    const int e = (blockIdx.x * blockDim.x + threadIdx.x) >> 5;
    const int lane = threadIdx.x & 31;
    if (e >= 2 * NTRI) return;
    const int idx = (e < NTRI) ? edges[2 * e] : edges[2 * (e - NTRI) + 1];
    const float ww = w[e];
    const float4* src = (const float4*)(cand + (size_t)e * H_);
    float* dst = pooled + (size_t)idx * H_;
    #pragma unroll
    for (int q = 0; q < 4; q++) {
        float4 v = src[lane + q * 32];
        float* d = dst + (size_t)(lane + q * 32) * 4;
        asm volatile("red.global.add.v4.f32 [%0], {%1, %2, %3, %4};"
                     :: "l"(d), "f"(v.x * ww), "f"(v.y * ww), "f"(v.z * ww), "f"(v.w * ww)
                     : "memory");
    }
}

extern "C" void kernel_launch(void* const* d_in, const int* in_sizes, int n_in,
                              void* d_out, int out_size)
{
    const float* obj    = (const float*)d_in[0];
    const float* pred   = (const float*)d_in[1];
    const int*   edges  = (const int*)d_in[2];
    const float* n1_w1  = (const float*)d_in[3];
    const float* n1_b1  = (const float*)d_in[4];
    const float* n1_w2  = (const float*)d_in[5];
    const float* n1_b2  = (const float*)d_in[6];
    const float* n2_w1  = (const float*)d_in[7];
    const float* n2_b1  = (const float*)d_in[8];
    const float* n2_w2  = (const float*)d_in[9];
    const float* n2_b2  = (const float*)d_in[10];
    const float* proj_w = (const float*)d_in[11];
    const float* proj_b = (const float*)d_in[12];
    const float* sim_w  = (const float*)d_in[13];
    const float* sim_b  = (const float*)d_in[14];

    float* out        = (float*)d_out;
    float* out_newobj = out;
    float* out_newp   = out + (size_t)NOBJ * DOUT_;

    float *cand, *pooled, *z, *scores, *w, *denom;
    unsigned* mkey;
    __nv_bfloat16 *objs, *preds, *h1s, *prevs, *pps, *us, *h2s;
    __nv_bfloat16 *wproj, *wsimT, *wsimN, *wn1a, *wn1b, *wn2a, *wn2b;
    cudaGetSymbolAddress((void**)&cand, g_cand);
    cudaGetSymbolAddress((void**)&pooled, g_pooled);
    cudaGetSymbolAddress((void**)&z, g_z);
    cudaGetSymbolAddress((void**)&mkey, g_mkey);
    cudaGetSymbolAddress((void**)&scores, g_scores);
    cudaGetSymbolAddress((void**)&w, g_w);
    cudaGetSymbolAddress((void**)&denom, g_denom);
    cudaGetSymbolAddress((void**)&objs, g_objs);
    cudaGetSymbolAddress((void**)&preds, g_preds);
    cudaGetSymbolAddress((void**)&h1s, g_h1s);
    cudaGetSymbolAddress((void**)&prevs, g_prevs);
    cudaGetSymbolAddress((void**)&pps, g_pps);
    cudaGetSymbolAddress((void**)&us, g_us);
    cudaGetSymbolAddress((void**)&h2s, g_h2s);
    cudaGetSymbolAddress((void**)&wproj, g_wproj);
    cudaGetSymbolAddress((void**)&wsimT, g_wsimT);
    cudaGetSymbolAddress((void**)&wsimN, g_wsimN);
    cudaGetSymbolAddress((void**)&wn1a, g_wn1a);
    cudaGetSymbolAddress((void**)&wn1b, g_wn1b);
    cudaGetSymbolAddress((void**)&wn2a, g_wn2a);
    cudaGetSymbolAddress((void**)&wn2b, g_wn2b);

    cudaFuncSetAttribute(mmak<0,1,false,true>,  cudaFuncAttributeMaxDynamicSharedMemorySize, SMEMB);
    cudaFuncSetAttribute(mmak<0,1,false,false>, cudaFuncAttributeMaxDynamicSharedMemorySize, SMEMB);
    cudaFuncSetAttribute(mmak<1,1,true,true>,   cudaFuncAttributeMaxDynamicSharedMemorySize, SMEMB);
    cudaFuncSetAttribute(mmak<0,2,true,true>,   cudaFuncAttributeMaxDynamicSharedMemorySize, SMEMB);
    cudaFuncSetAttribute(mmak<2,1,true,true>,   cudaFuncAttributeMaxDynamicSharedMemorySize, SMEMB);
    cudaFuncSetAttribute(mmak<0,0,true,true>,   cudaFuncAttributeMaxDynamicSharedMemorySize, SMEMB);

    const int gO = (NOBJ + 127) / 128;   // 391
    const int gT = (NTRI + 127) / 128;   // 782
    const dim3 blk(256);

    // splits (tiny)
    isplit<<<(NOBJ * DIN_ + 255) / 256, 256>>>(obj, objs, NOBJ * DIN_);
    isplit<<<(NTRI * DIN_ + 255) / 256, 256>>>(pred, preds, NTRI * DIN_);
    wsplitT<<<(512 * 128 + 255) / 256, 256>>>(proj_w, wproj, 128, 512);
    wsplitT<<<(512 * 512 + 255) / 256, 256>>>(sim_w, wsimT, 512, 512);
    wsplitN<<<(512 * 512 + 255) / 256, 256>>>(sim_w, wsimN, 512 * 512);
    wsplitT<<<(512 * 384 + 255) / 256, 256>>>(n1_w1, wn1a, 384, 512);
    wsplitT<<<(1152 * 512 + 255) / 256, 256>>>(n1_w2, wn1b, 512, 1152);
    wsplitT<<<(512 * 512 + 255) / 256, 256>>>(n2_w1, wn2a, 512, 512);
    wsplitT<<<(512 * 128 + 255) / 256, 256>>>(n2_w2, wn2b, 512, 128);

    // object-side projections (outputs written as split planes)
    mmak<0,1,false,true><<<dim3(4, gO), blk, SMEMB>>>(objs, nullptr, wproj, proj_b, nullptr, prevs,
        NOBJ, 512, 128, nullptr, nullptr, nullptr, nullptr, nullptr, nullptr);
    mmak<0,1,false,true><<<dim3(4, gO), blk, SMEMB>>>(prevs, nullptr, wsimT, sim_b, nullptr, pps,
        NOBJ, 512, 512, nullptr, nullptr, nullptr, nullptr, nullptr, nullptr);
    mmak<0,1,false,false><<<dim3(4, gO), blk, SMEMB>>>(pps, nullptr, wsimN, nullptr, nullptr, us,
        NOBJ, 512, 512, nullptr, nullptr, nullptr, nullptr, nullptr, nullptr);
    zk2<<<(NOBJ * 32 + 255) / 256, 256>>>(pps, sim_b, z, mkey);

    // triple MLP
    mmak<1,1,true,true><<<dim3(4, gT), blk, SMEMB>>>(nullptr, nullptr, wn1a, n1_b1, nullptr, h1s,
        NTRI, 512, 384, objs, preds, edges, nullptr, nullptr, nullptr);
    mmak<0,2,true,true><<<dim3(9, gT), blk, SMEMB>>>(h1s, nullptr, wn1b, n1_b2, nullptr, nullptr,
        NTRI, 1152, 512, nullptr, nullptr, nullptr, nullptr, out_newp, cand);

    // attention scores + segment softmax
    scorek2<<<(2 * NTRI + 7) / 8, 256>>>(cand, us, z, edges, scores, mkey);
    zerok<<<2048, 256>>>(pooled, (size_t)NOBJ * H_);
    dinitk<<<(NOBJ + 255) / 256, 256>>>(z, mkey, denom);
    wk<<<(2 * NTRI + 255) / 256, 256>>>(scores, mkey, edges, w, denom);
    poolk<<<(2 * NTRI + 7) / 8, 256>>>(cand, w, edges, pooled);

    // output MLP
    mmak<2,1,true,true><<<dim3(4, gO), blk, SMEMB>>>(nullptr, pooled, wn2a, n2_b1, nullptr, h2s,
        NOBJ, 512, 512, nullptr, nullptr, nullptr, denom, nullptr, nullptr);
    mmak<0,0,true,true><<<dim3(1, gO), blk, SMEMB>>>(h2s, nullptr, wn2b, n2_b2, out_newobj, nullptr,
        NOBJ, 128, 512, nullptr, nullptr, nullptr, nullptr, nullptr, nullptr);
}

// round 6
// speedup vs baseline: 2.4275x; 1.2407x over previous
#include <cuda_runtime.h>
#include <cuda_bf16.h>
#include <math.h>
#include <stdint.h>

#define NOBJ 50000
#define NTRI 100000
#define DIN_ 128
#define H_   512
#define DOUT_ 128

// ---------------- scratch (device globals: no allocs allowed) ----------------
static __device__ float    g_cand[(size_t)2 * NTRI * H_];   // fp32 (scorek/poolk)
static __device__ float    g_pooled[(size_t)NOBJ * H_];
static __device__ float    g_z[NOBJ];
static __device__ unsigned g_mkey[NOBJ];
static __device__ float    g_scores[2 * NTRI];
static __device__ float    g_w[2 * NTRI];
static __device__ float    g_denom[NOBJ];

// 2-term bf16 split planes [2][M][K]
static __device__ __nv_bfloat16 g_objs [(size_t)2 * NOBJ * DIN_];
static __device__ __nv_bfloat16 g_preds[(size_t)2 * NTRI * DIN_];
static __device__ __nv_bfloat16 g_h1s  [(size_t)2 * NTRI * H_];
static __device__ __nv_bfloat16 g_prevs[(size_t)2 * NOBJ * H_];
static __device__ __nv_bfloat16 g_pps  [(size_t)2 * NOBJ * H_];
static __device__ __nv_bfloat16 g_us   [(size_t)2 * NOBJ * H_];
static __device__ __nv_bfloat16 g_h2s  [(size_t)2 * NOBJ * H_];

// 2-term bf16 split weights, [2][N][K]
static __device__ __nv_bfloat16 g_wproj[2 * 512 * 128];
static __device__ __nv_bfloat16 g_wsimT[2 * 512 * 512];
static __device__ __nv_bfloat16 g_wsimN[2 * 512 * 512];
static __device__ __nv_bfloat16 g_wn1a[2 * 512 * 384];
static __device__ __nv_bfloat16 g_wn1b[2 * 1152 * 512];
static __device__ __nv_bfloat16 g_wn2a[2 * 512 * 512];
static __device__ __nv_bfloat16 g_wn2b[2 * 128 * 512];

// ---------------- helpers ----------------
__device__ __forceinline__ void split2(float x, unsigned short& hi, unsigned short& lo) {
    __nv_bfloat16 h = __float2bfloat16_rn(x);
    __nv_bfloat16 l = __float2bfloat16_rn(x - __bfloat162float(h));
    hi = __bfloat16_as_ushort(h);
    lo = __bfloat16_as_ushort(l);
}
__device__ __forceinline__ float2 bf2(uint32_t u) {
    return make_float2(__bfloat162float(__ushort_as_bfloat16((unsigned short)(u & 0xffff))),
                       __bfloat162float(__ushort_as_bfloat16((unsigned short)(u >> 16))));
}
__device__ __forceinline__ uint32_t smem_u32(const void* p) {
    uint32_t a;
    asm("{ .reg .u64 t; cvta.to.shared.u64 t, %1; cvt.u32.u64 %0, t; }" : "=r"(a) : "l"(p));
    return a;
}
__device__ __forceinline__ void cpa16(uint32_t dst, const void* src, uint32_t sz) {
    asm volatile("cp.async.cg.shared.global [%0], [%1], 16, %2;"
                 :: "r"(dst), "l"(src), "r"(sz) : "memory");
}
#define CPA_COMMIT() asm volatile("cp.async.commit_group;" ::: "memory")
#define CPA_WAIT0()  asm volatile("cp.async.wait_group 0;" ::: "memory")

__device__ __forceinline__ void mma16816(float* d, const uint32_t* a, uint32_t b0, uint32_t b1) {
    asm volatile(
        "mma.sync.aligned.m16n8k16.row.col.f32.bf16.bf16.f32 "
        "{%0,%1,%2,%3}, {%4,%5,%6,%7}, {%8,%9}, {%0,%1,%2,%3};"
        : "+f"(d[0]), "+f"(d[1]), "+f"(d[2]), "+f"(d[3])
        : "r"(a[0]), "r"(a[1]), "r"(a[2]), "r"(a[3]), "r"(b0), "r"(b1));
}
__device__ __forceinline__ void ldsm4(uint32_t* r, uint32_t addr) {
    asm volatile("ldmatrix.sync.aligned.m8n8.x4.shared.b16 {%0,%1,%2,%3}, [%4];"
                 : "=r"(r[0]), "=r"(r[1]), "=r"(r[2]), "=r"(r[3]) : "r"(addr));
}

// weight split kernels: out[2][Nd][Kd]
__global__ void wsplitT(const float* __restrict__ W, __nv_bfloat16* __restrict__ out,
                        int Kd, int Nd) {
    const int idx = blockIdx.x * blockDim.x + threadIdx.x;
    const size_t NK = (size_t)Nd * Kd;
    if (idx >= (int)NK) return;
    const int n = idx / Kd, k = idx - n * Kd;
    unsigned short a, b;
    split2(W[(size_t)k * Nd + n], a, b);
    out[idx]      = __ushort_as_bfloat16(a);
    out[NK + idx] = __ushort_as_bfloat16(b);
}
__global__ void wsplitN(const float* __restrict__ W, __nv_bfloat16* __restrict__ out,
                        int total) {
    const int idx = blockIdx.x * blockDim.x + threadIdx.x;
    if (idx >= total) return;
    unsigned short a, b;
    split2(W[idx], a, b);
    out[idx]         = __ushort_as_bfloat16(a);
    out[total + idx] = __ushort_as_bfloat16(b);
}
// input split: dst[2][n]
__global__ void isplit(const float* __restrict__ src, __nv_bfloat16* __restrict__ dst, int n) {
    const int i = blockIdx.x * blockDim.x + threadIdx.x;
    if (i >= n) return;
    unsigned short a, b;
    split2(src[i], a, b);
    dst[i]     = __ushort_as_bfloat16(a);
    dst[n + i] = __ushort_as_bfloat16(b);
}

// ---------------- HMMA GEMM: D[M,N] = A[M,K] @ Ws^T ----------------
// AMODE: 0 A = split planes As[2][M][K]; 1 gather split [objs|preds|objs] (K=384);
//        2 A = fp32 Af scaled by 1/denom[m] (runtime split)
// OMODE: 0 fp32 C; 1 split planes Cs[2][M][N]; 2 split N=1152 -> cand / out_newp / cand+T (fp32)
// 256 thr (2x4 warps), CTA tile 128x128, warp tile 64x32, BK=32, double-buffered cp.async.
// Fragment loads via ldmatrix.x4 (80B pitch -> conflict-free).
#define APITCH 80
#define PLANE  (128 * APITCH)                 // 10240 B
#define SMEMB  (8 * PLANE)                    // 81920 B

template<int AMODE, int OMODE, bool RELU, bool HASBIAS>
__global__ __launch_bounds__(256, 2)
void mmak(const __nv_bfloat16* __restrict__ As, const float* __restrict__ Af,
          const __nv_bfloat16* __restrict__ Wt,
          const float* __restrict__ bias, float* __restrict__ Cf,
          __nv_bfloat16* __restrict__ Cs,
          int M, int N, int K,
          const __nv_bfloat16* __restrict__ objs, const __nv_bfloat16* __restrict__ preds,
          const int* __restrict__ edges, const float* __restrict__ denomv,
          float* __restrict__ outp, float* __restrict__ candp)
{
    extern __shared__ __align__(16) unsigned char sm[];
    const int tid = threadIdx.x;
    const int lane = tid & 31, wid = tid >> 5;
    const int wr = wid >> 2, wc = wid & 3;
    const int bm = blockIdx.y * 128, bn = blockIdx.x * 128;
    const size_t MK = (size_t)M * K, NK = (size_t)N * K, MN = (size_t)M * N;
    const uint32_t sb = smem_u32(sm);
    const int arow = lane >> 2, acol = (lane & 3) << 1;
    const int t8 = lane & 7, quad = lane >> 3;

    // ldmatrix base offsets (within one buffer)
    const uint32_t aoff = (uint32_t)(wr * 64 + t8 + ((quad & 1) << 3)) * APITCH + ((quad >> 1) << 4);
    const uint32_t boff = 2 * PLANE +
        (uint32_t)(wc * 32 + t8 + ((quad >> 1) << 3)) * APITCH + ((quad & 1) << 4);

    float acc[4][4][4];
    #pragma unroll
    for (int i = 0; i < 4; i++)
        #pragma unroll
        for (int j = 0; j < 4; j++)
            #pragma unroll
            for (int q = 0; q < 4; q++) acc[i][j][q] = 0.f;

    float4 pf[4];  // AMODE2 prefetch

    auto stageAsync = [&](int k0, int b) {
        const uint32_t smA = sb + b * 4 * PLANE;
        const uint32_t smB = smA + 2 * PLANE;
        if (AMODE == 0) {
            #pragma unroll
            for (int it = 0; it < 4; it++) {
                const int idx = (it << 8) + tid;
                const int p = idx >> 9, r = (idx >> 2) & 127, seg = idx & 3;
                const int gm = bm + r;
                const int gmc = gm < M ? gm : M - 1;
                const __nv_bfloat16* src = As + (size_t)p * MK + (size_t)gmc * K + k0 + seg * 8;
                cpa16(smA + p * PLANE + r * APITCH + seg * 16, src, gm < M ? 16u : 0u);
            }
        } else if (AMODE == 1) {
            #pragma unroll
            for (int it = 0; it < 4; it++) {
                const int idx = (it << 8) + tid;
                const int p = idx >> 9, r = (idx >> 2) & 127, seg = idx & 3;
                const int gm = bm + r;
                const int gmc = gm < M ? gm : M - 1;
                const __nv_bfloat16* src;
                if (k0 < DIN_)
                    src = objs + (size_t)p * ((size_t)NOBJ * DIN_)
                        + (size_t)edges[2 * gmc] * DIN_ + k0 + seg * 8;
                else if (k0 < 2 * DIN_)
                    src = preds + (size_t)p * ((size_t)NTRI * DIN_)
                        + (size_t)gmc * DIN_ + (k0 - DIN_) + seg * 8;
                else
                    src = objs + (size_t)p * ((size_t)NOBJ * DIN_)
                        + (size_t)edges[2 * gmc + 1] * DIN_ + (k0 - 2 * DIN_) + seg * 8;
                cpa16(smA + p * PLANE + r * APITCH + seg * 16, src, gm < M ? 16u : 0u);
            }
        }
        #pragma unroll
        for (int it = 0; it < 4; it++) {
            const int idx = (it << 8) + tid;
            const int p = idx >> 9, n = (idx >> 2) & 127, seg = idx & 3;
            const __nv_bfloat16* src = Wt + (size_t)p * NK + (size_t)(bn + n) * K + k0 + seg * 8;
            cpa16(smB + p * PLANE + n * APITCH + seg * 16, src, 16u);
        }
        CPA_COMMIT();
    };

    auto loadA2 = [&](int k0) {
        #pragma unroll
        for (int it = 0; it < 4; it++) {
            const int idx = (it << 8) + tid;
            const int m = idx >> 3, q = idx & 7;
            const int gm = bm + m;
            float4 v = make_float4(0.f, 0.f, 0.f, 0.f);
            if (gm < M) {
                v = *(const float4*)(Af + (size_t)gm * K + k0 + (q << 2));
                const float sc = __fdividef(1.f, denomv[gm]);
                v.x *= sc; v.y *= sc; v.z *= sc; v.w *= sc;
            }
            pf[it] = v;
        }
    };
    auto stsA2 = [&](int b) {
        unsigned char* smA = sm + b * 4 * PLANE;
        #pragma unroll
        for (int it = 0; it < 4; it++) {
            const int idx = (it << 8) + tid;
            const int m = idx >> 3, q = idx & 7;
            unsigned short h[4], l[4];
            split2(pf[it].x, h[0], l[0]); split2(pf[it].y, h[1], l[1]);
            split2(pf[it].z, h[2], l[2]); split2(pf[it].w, h[3], l[3]);
            const int boff2 = m * APITCH + (q << 3);
            *(uint2*)(smA + boff2) = make_uint2((uint32_t)h[0] | ((uint32_t)h[1] << 16),
                                                (uint32_t)h[2] | ((uint32_t)h[3] << 16));
            *(uint2*)(smA + PLANE + boff2) = make_uint2((uint32_t)l[0] | ((uint32_t)l[1] << 16),
                                                        (uint32_t)l[2] | ((uint32_t)l[3] << 16));
        }
    };

    auto compute = [&](int b) {
        const uint32_t buf = sb + b * 4 * PLANE;
        #pragma unroll
        for (int s = 0; s < 2; s++) {
            const uint32_t ksb = s * 32;   // 16 bf16 = 32 bytes
            uint32_t af[2][4][4];
            #pragma unroll
            for (int p = 0; p < 2; p++)
                #pragma unroll
                for (int i = 0; i < 4; i++)
                    ldsm4(af[p][i], buf + p * PLANE + aoff + i * 16 * APITCH + ksb);
            uint32_t bfr[2][4][2];
            #pragma unroll
            for (int p = 0; p < 2; p++)
                #pragma unroll
                for (int jj = 0; jj < 2; jj++)
                    ldsm4(&bfr[p][jj * 2][0], buf + p * PLANE + boff + jj * 16 * APITCH + ksb);
            // product-major ordering: 16 independent accumulators between reuses
            #pragma unroll
            for (int j = 0; j < 4; j++)
                #pragma unroll
                for (int i = 0; i < 4; i++)
                    mma16816(acc[i][j], af[0][i], bfr[0][j][0], bfr[0][j][1]);
            #pragma unroll
            for (int j = 0; j < 4; j++)
                #pragma unroll
                for (int i = 0; i < 4; i++)
                    mma16816(acc[i][j], af[1][i], bfr[0][j][0], bfr[0][j][1]);
            #pragma unroll
            for (int j = 0; j < 4; j++)
                #pragma unroll
                for (int i = 0; i < 4; i++)
                    mma16816(acc[i][j], af[0][i], bfr[1][j][0], bfr[1][j][1]);
        }
    };

    const int nch = K >> 5;
    stageAsync(0, 0);
    if (AMODE == 2) { loadA2(0); stsA2(0); }
    CPA_WAIT0();
    __syncthreads();

    for (int ch = 0; ch < nch; ch++) {
        const int b = ch & 1;
        const bool nxt = (ch + 1) < nch;
        if (nxt) {
            stageAsync((ch + 1) << 5, b ^ 1);
            if (AMODE == 2) loadA2((ch + 1) << 5);
        }
        compute(b);
        if (nxt && AMODE == 2) stsA2(b ^ 1);
        CPA_WAIT0();
        __syncthreads();
    }

    // ---- epilogue ----
    #pragma unroll
    for (int i = 0; i < 4; i++)
        #pragma unroll
        for (int j = 0; j < 4; j++) {
            const int gm0 = bm + wr * 64 + i * 16 + arow;
            const int gn  = bn + wc * 32 + j * 8 + acol;
            float2 bb = make_float2(0.f, 0.f);
            if (HASBIAS) bb = *(const float2*)&bias[gn];
            #pragma unroll
            for (int h = 0; h < 2; h++) {
                const int m = gm0 + h * 8;
                if (m < M) {
                    float x0 = acc[i][j][2 * h]     + bb.x;
                    float x1 = acc[i][j][2 * h + 1] + bb.y;
                    if (RELU) { x0 = fmaxf(x0, 0.f); x1 = fmaxf(x1, 0.f); }
                    if (OMODE == 0) {
                        *(float2*)(Cf + (size_t)m * N + gn) = make_float2(x0, x1);
                    } else if (OMODE == 1) {
                        unsigned short h0, l0, h1, l1;
                        split2(x0, h0, l0); split2(x1, h1, l1);
                        *(uint32_t*)(Cs + (size_t)m * N + gn)      = (uint32_t)h0 | ((uint32_t)h1 << 16);
                        *(uint32_t*)(Cs + MN + (size_t)m * N + gn) = (uint32_t)l0 | ((uint32_t)l1 << 16);
                    } else {
                        float* dst;
                        if (gn < H_)              dst = candp + (size_t)m * H_ + gn;
                        else if (gn < H_ + DOUT_) dst = outp + (size_t)m * DOUT_ + (gn - H_);
                        else                      dst = candp + (size_t)(NTRI + m) * H_ + (gn - H_ - DOUT_);
                        *(float2*)dst = make_float2(x0, x1);
                    }
                }
            }
        }
}

// ---------------- softmax / pooling kernels ----------------
__device__ __forceinline__ unsigned fenc(float f) {
    unsigned u = __float_as_uint(f);
    return (u & 0x80000000u) ? ~u : (u | 0x80000000u);
}
__device__ __forceinline__ float fdec(unsigned e) {
    unsigned u = (e & 0x80000000u) ? (e & 0x7fffffffu) : ~e;
    return __uint_as_float(u);
}

// z[i] = (pps_hi[i]+pps_lo[i]) . sim_b ; seed mkey
__global__ void zk2(const __nv_bfloat16* __restrict__ pps, const float* __restrict__ simb,
                    float* __restrict__ z, unsigned* __restrict__ mkey)
{
    const int row = (blockIdx.x * blockDim.x + threadIdx.x) >> 5;
    const int lane = threadIdx.x & 31;
    if (row >= NOBJ) return;
    const size_t PS = (size_t)NOBJ * H_;
    const uint2* ph = (const uint2*)(pps + (size_t)row * H_);
    const uint2* pl = (const uint2*)(pps + PS + (size_t)row * H_);
    float s = 0.f;
    #pragma unroll
    for (int q = 0; q < 4; q++) {
        const int t = lane + q * 32;
        uint2 a = ph[t], b = pl[t];
        float4 w4 = *(const float4*)&simb[t * 4];
        float2 a0 = bf2(a.x), a1 = bf2(a.y), b0 = bf2(b.x), b1 = bf2(b.y);
        s += (a0.x + b0.x) * w4.x + (a0.y + b0.y) * w4.y
           + (a1.x + b1.x) * w4.z + (a1.y + b1.y) * w4.w;
    }
    #pragma unroll
    for (int o = 16; o; o >>= 1) s += __shfl_down_sync(0xffffffffu, s, o);
    if (lane == 0) { z[row] = s; mkey[row] = fenc(s); }
}

// scores[e] = cand[e] . (us_hi+us_lo)[idx] + z[idx];  atomicMax into mkey
__global__ void scorek2(const float* __restrict__ cand, const __nv_bfloat16* __restrict__ us,
                        const float* __restrict__ z, const int* __restrict__ edges,
                        float* __restrict__ scores, unsigned* __restrict__ mkey)
{
    const int e = (blockIdx.x * blockDim.x + threadIdx.x) >> 5;
    const int lane = threadIdx.x & 31;
    if (e >= 2 * NTRI) return;
    const int idx = (e < NTRI) ? edges[2 * e] : edges[2 * (e - NTRI) + 1];
    const size_t PS = (size_t)NOBJ * H_;
    const float4* a = (const float4*)(cand + (size_t)e * H_);
    const uint2* uh = (const uint2*)(us + (size_t)idx * H_);
    const uint2* ul = (const uint2*)(us + PS + (size_t)idx * H_);
    float s = 0.f;
    #pragma unroll
    for (int q = 0; q < 4; q++) {
        const int t = lane + q * 32;
        float4 x = a[t];
        uint2 hu = uh[t], lu = ul[t];
        float2 h0 = bf2(hu.x), h1 = bf2(hu.y), l0 = bf2(lu.x), l1 = bf2(lu.y);
        s += x.x * (h0.x + l0.x) + x.y * (h0.y + l0.y)
           + x.z * (h1.x + l1.x) + x.w * (h1.y + l1.y);
    }
    #pragma unroll
    for (int o = 16; o; o >>= 1) s += __shfl_down_sync(0xffffffffu, s, o);
    if (lane == 0) {
        const float sc = s + z[idx];
        scores[e] = sc;
        atomicMax(mkey + idx, fenc(sc));
    }
}

__global__ void zerok(float* __restrict__ p, size_t n)
{
    size_t i = (size_t)blockIdx.x * blockDim.x + threadIdx.x;
    const size_t stride = (size_t)gridDim.x * blockDim.x;
    for (; i < n; i += stride) p[i] = 0.f;
}

__global__ void dinitk(const float* __restrict__ z, const unsigned* __restrict__ mkey,
                       float* __restrict__ denom)
{
    const int i = blockIdx.x * blockDim.x + threadIdx.x;
    if (i < NOBJ) denom[i] = expf(z[i] - fdec(mkey[i]));
}

__global__ void wk(const float* __restrict__ scores, const unsigned* __restrict__ mkey,
                   const int* __restrict__ edges, float* __restrict__ w,
                   float* __restrict__ denom)
{
    const int e = blockIdx.x * blockDim.x + threadIdx.x;
    if (e >= 2 * NTRI) return;
    const int idx = (e < NTRI) ? edges[2 * e] : edges[2 * (e - NTRI) + 1];
    const float ww = expf(scores[e] - fdec(mkey[idx]));
    w[e] = ww;
    atomicAdd(denom + idx, ww);
}

__global__ void poolk(const float* __restrict__ cand, const float* __restrict__ w,
                      const int* __restrict__ edges, float* __restrict__ pooled)
{
    const int e = (blockIdx.x * blockDim.x + threadIdx.x) >> 5;
    const int lane = threadIdx.x & 31;
    if (e >= 2 * NTRI) return;
    const int idx = (e < NTRI) ? edges[2 * e] : edges[2 * (e - NTRI) + 1];
    const float ww = w[e];
    const float4* src = (const float4*)(cand + (size_t)e * H_);
    float* dst = pooled + (size_t)idx * H_;
    #pragma unroll
    for (int q = 0; q < 4; q++) {
        float4 v = src[lane + q * 32];
        float* d = dst + (size_t)(lane + q * 32) * 4;
        asm volatile("red.global.add.v4.f32 [%0], {%1, %2, %3, %4};"
                     :: "l"(d), "f"(v.x * ww), "f"(v.y * ww), "f"(v.z * ww), "f"(v.w * ww)
                     : "memory");
    }
}

extern "C" void kernel_launch(void* const* d_in, const int* in_sizes, int n_in,
                              void* d_out, int out_size)
{
    const float* obj    = (const float*)d_in[0];
    const float* pred   = (const float*)d_in[1];
    const int*   edges  = (const int*)d_in[2];
    const float* n1_w1  = (const float*)d_in[3];
    const float* n1_b1  = (const float*)d_in[4];
    const float* n1_w2  = (const float*)d_in[5];
    const float* n1_b2  = (const float*)d_in[6];
    const float* n2_w1  = (const float*)d_in[7];
    const float* n2_b1  = (const float*)d_in[8];
    const float* n2_w2  = (const float*)d_in[9];
    const float* n2_b2  = (const float*)d_in[10];
    const float* proj_w = (const float*)d_in[11];
    const float* proj_b = (const float*)d_in[12];
    const float* sim_w  = (const float*)d_in[13];
    const float* sim_b  = (const float*)d_in[14];

    float* out        = (float*)d_out;
    float* out_newobj = out;
    float* out_newp   = out + (size_t)NOBJ * DOUT_;

    float *cand, *pooled, *z, *scores, *w, *denom;
    unsigned* mkey;
    __nv_bfloat16 *objs, *preds, *h1s, *prevs, *pps, *us, *h2s;
    __nv_bfloat16 *wproj, *wsimT, *wsimN, *wn1a, *wn1b, *wn2a, *wn2b;
    cudaGetSymbolAddress((void**)&cand, g_cand);
    cudaGetSymbolAddress((void**)&pooled, g_pooled);
    cudaGetSymbolAddress((void**)&z, g_z);
    cudaGetSymbolAddress((void**)&mkey, g_mkey);
    cudaGetSymbolAddress((void**)&scores, g_scores);
    cudaGetSymbolAddress((void**)&w, g_w);
    cudaGetSymbolAddress((void**)&denom, g_denom);
    cudaGetSymbolAddress((void**)&objs, g_objs);
    cudaGetSymbolAddress((void**)&preds, g_preds);
    cudaGetSymbolAddress((void**)&h1s, g_h1s);
    cudaGetSymbolAddress((void**)&prevs, g_prevs);
    cudaGetSymbolAddress((void**)&pps, g_pps);
    cudaGetSymbolAddress((void**)&us, g_us);
    cudaGetSymbolAddress((void**)&h2s, g_h2s);
    cudaGetSymbolAddress((void**)&wproj, g_wproj);
    cudaGetSymbolAddress((void**)&wsimT, g_wsimT);
    cudaGetSymbolAddress((void**)&wsimN, g_wsimN);
    cudaGetSymbolAddress((void**)&wn1a, g_wn1a);
    cudaGetSymbolAddress((void**)&wn1b, g_wn1b);
    cudaGetSymbolAddress((void**)&wn2a, g_wn2a);
    cudaGetSymbolAddress((void**)&wn2b, g_wn2b);

    cudaFuncSetAttribute(mmak<0,1,false,true>,  cudaFuncAttributeMaxDynamicSharedMemorySize, SMEMB);
    cudaFuncSetAttribute(mmak<0,1,false,false>, cudaFuncAttributeMaxDynamicSharedMemorySize, SMEMB);
    cudaFuncSetAttribute(mmak<1,1,true,true>,   cudaFuncAttributeMaxDynamicSharedMemorySize, SMEMB);
    cudaFuncSetAttribute(mmak<0,2,true,true>,   cudaFuncAttributeMaxDynamicSharedMemorySize, SMEMB);
    cudaFuncSetAttribute(mmak<2,1,true,true>,   cudaFuncAttributeMaxDynamicSharedMemorySize, SMEMB);
    cudaFuncSetAttribute(mmak<0,0,true,true>,   cudaFuncAttributeMaxDynamicSharedMemorySize, SMEMB);

    const int gO = (NOBJ + 127) / 128;   // 391
    const int gT = (NTRI + 127) / 128;   // 782
    const dim3 blk(256);

    // Launch-order note: ncu profiles launch #6 (-s 5 -c 1). Order the first
    // five launches as prerequisites of the gather GEMM so #6 = mmak(n1a).
    wsplitT<<<(512 * 384 + 255) / 256, 256>>>(n1_w1, wn1a, 384, 512);          // 1
    isplit<<<(NOBJ * DIN_ + 255) / 256, 256>>>(obj, objs, NOBJ * DIN_);        // 2
    isplit<<<(NTRI * DIN_ + 255) / 256, 256>>>(pred, preds, NTRI * DIN_);      // 3
    wsplitT<<<(1152 * 512 + 255) / 256, 256>>>(n1_w2, wn1b, 512, 1152);        // 4
    wsplitT<<<(512 * 128 + 255) / 256, 256>>>(proj_w, wproj, 128, 512);        // 5

    // 6: triple MLP layer 1 (gather GEMM) — profiled
    mmak<1,1,true,true><<<dim3(4, gT), blk, SMEMB>>>(nullptr, nullptr, wn1a, n1_b1, nullptr, h1s,
        NTRI, 512, 384, objs, preds, edges, nullptr, nullptr, nullptr);

    // remaining weight splits
    wsplitT<<<(512 * 512 + 255) / 256, 256>>>(sim_w, wsimT, 512, 512);
    wsplitN<<<(512 * 512 + 255) / 256, 256>>>(sim_w, wsimN, 512 * 512);
    wsplitT<<<(512 * 512 + 255) / 256, 256>>>(n2_w1, wn2a, 512, 512);
    wsplitT<<<(512 * 128 + 255) / 256, 256>>>(n2_w2, wn2b, 512, 128);

    // triple MLP layer 2 (split outputs into cand / new_p)
    mmak<0,2,true,true><<<dim3(9, gT), blk, SMEMB>>>(h1s, nullptr, wn1b, n1_b2, nullptr, nullptr,
        NTRI, 1152, 512, nullptr, nullptr, nullptr, nullptr, out_newp, cand);

    // object-side projections
    mmak<0,1,false,true><<<dim3(4, gO), blk, SMEMB>>>(objs, nullptr, wproj, proj_b, nullptr, prevs,
        NOBJ, 512, 128, nullptr, nullptr, nullptr, nullptr, nullptr, nullptr);
    mmak<0,1,false,true><<<dim3(4, gO), blk, SMEMB>>>(prevs, nullptr, wsimT, sim_b, nullptr, pps,
        NOBJ, 512, 512, nullptr, nullptr, nullptr, nullptr, nullptr, nullptr);
    mmak<0,1,false,false><<<dim3(4, gO), blk, SMEMB>>>(pps, nullptr, wsimN, nullptr, nullptr, us,
        NOBJ, 512, 512, nullptr, nullptr, nullptr, nullptr, nullptr, nullptr);
    zk2<<<(NOBJ * 32 + 255) / 256, 256>>>(pps, sim_b, z, mkey);

    // attention scores + segment softmax
    scorek2<<<(2 * NTRI + 7) / 8, 256>>>(cand, us, z, edges, scores, mkey);
    zerok<<<2048, 256>>>(pooled, (size_t)NOBJ * H_);
    dinitk<<<(NOBJ + 255) / 256, 256>>>(z, mkey, denom);
    wk<<<(2 * NTRI + 255) / 256, 256>>>(scores, mkey, edges, w, denom);
    poolk<<<(2 * NTRI + 7) / 8, 256>>>(cand, w, edges, pooled);

    // output MLP
    mmak<2,1,true,true><<<dim3(4, gO), blk, SMEMB>>>(nullptr, pooled, wn2a, n2_b1, nullptr, h2s,
        NOBJ, 512, 512, nullptr, nullptr, nullptr, denom, nullptr, nullptr);
    mmak<0,0,true,true><<<dim3(1, gO), blk, SMEMB>>>(h2s, nullptr, wn2b, n2_b2, out_newobj, nullptr,
        NOBJ, 128, 512, nullptr, nullptr, nullptr, nullptr, nullptr, nullptr);
}

// round 7
// speedup vs baseline: 2.6462x; 1.0901x over previous
#include <cuda_runtime.h>
#include <cuda_bf16.h>
#include <math.h>
#include <stdint.h>

#define NOBJ 50000
#define NTRI 100000
#define DIN_ 128
#define H_   512
#define DOUT_ 128

// ---------------- scratch (device globals: no allocs allowed) ----------------
static __device__ float    g_cand[(size_t)2 * NTRI * H_];   // fp32 (scorek/poolk)
static __device__ float    g_pooled[(size_t)NOBJ * H_];
static __device__ float    g_z[NOBJ];
static __device__ unsigned g_mkey[NOBJ];
static __device__ float    g_scores[2 * NTRI];
static __device__ float    g_denom[NOBJ];
static __device__ float    g_bu[H_];
static __device__ float    g_c0[1];

// 2-term bf16 split planes [2][M][K]
static __device__ __nv_bfloat16 g_objs [(size_t)2 * NOBJ * DIN_];
static __device__ __nv_bfloat16 g_preds[(size_t)2 * NTRI * DIN_];
static __device__ __nv_bfloat16 g_h1s  [(size_t)2 * NTRI * H_];
static __device__ __nv_bfloat16 g_prevs[(size_t)2 * NOBJ * H_];
static __device__ __nv_bfloat16 g_us   [(size_t)2 * NOBJ * H_];
static __device__ __nv_bfloat16 g_h2s  [(size_t)2 * NOBJ * H_];
static __device__ __nv_bfloat16 g_simws[2 * 512 * 512];     // sim_w rows, split
static __device__ __nv_bfloat16 g_Ss   [2 * 512 * 512];     // S = sim_w@sim_w^T, split

// 2-term bf16 split weights, [2][N][K]
static __device__ __nv_bfloat16 g_wproj[2 * 512 * 128];
static __device__ __nv_bfloat16 g_wn1a[2 * 512 * 384];
static __device__ __nv_bfloat16 g_wn1b[2 * 1152 * 512];
static __device__ __nv_bfloat16 g_wn2a[2 * 512 * 512];
static __device__ __nv_bfloat16 g_wn2b[2 * 128 * 512];

// ---------------- helpers ----------------
__device__ __forceinline__ void split2(float x, unsigned short& hi, unsigned short& lo) {
    __nv_bfloat16 h = __float2bfloat16_rn(x);
    __nv_bfloat16 l = __float2bfloat16_rn(x - __bfloat162float(h));
    hi = __bfloat16_as_ushort(h);
    lo = __bfloat16_as_ushort(l);
}
__device__ __forceinline__ float2 bf2(uint32_t u) {
    return make_float2(__bfloat162float(__ushort_as_bfloat16((unsigned short)(u & 0xffff))),
                       __bfloat162float(__ushort_as_bfloat16((unsigned short)(u >> 16))));
}
__device__ __forceinline__ uint32_t smem_u32(const void* p) {
    uint32_t a;
    asm("{ .reg .u64 t; cvta.to.shared.u64 t, %1; cvt.u32.u64 %0, t; }" : "=r"(a) : "l"(p));
    return a;
}
__device__ __forceinline__ void cpa16(uint32_t dst, const void* src, uint32_t sz) {
    asm volatile("cp.async.cg.shared.global [%0], [%1], 16, %2;"
                 :: "r"(dst), "l"(src), "r"(sz) : "memory");
}
#define CPA_COMMIT() asm volatile("cp.async.commit_group;" ::: "memory")
#define CPA_WAIT0()  asm volatile("cp.async.wait_group 0;" ::: "memory")

__device__ __forceinline__ void mma16816(float* d, const uint32_t* a, uint32_t b0, uint32_t b1) {
    asm volatile(
        "mma.sync.aligned.m16n8k16.row.col.f32.bf16.bf16.f32 "
        "{%0,%1,%2,%3}, {%4,%5,%6,%7}, {%8,%9}, {%0,%1,%2,%3};"
        : "+f"(d[0]), "+f"(d[1]), "+f"(d[2]), "+f"(d[3])
        : "r"(a[0]), "r"(a[1]), "r"(a[2]), "r"(a[3]), "r"(b0), "r"(b1));
}
__device__ __forceinline__ void ldsm4(uint32_t* r, uint32_t addr) {
    asm volatile("ldmatrix.sync.aligned.m8n8.x4.shared.b16 {%0,%1,%2,%3}, [%4];"
                 : "=r"(r[0]), "=r"(r[1]), "=r"(r[2]), "=r"(r[3]) : "r"(addr));
}

// weight split kernels: out[2][Nd][Kd]
__global__ void wsplitT(const float* __restrict__ W, __nv_bfloat16* __restrict__ out,
                        int Kd, int Nd) {
    const int idx = blockIdx.x * blockDim.x + threadIdx.x;
    const size_t NK = (size_t)Nd * Kd;
    if (idx >= (int)NK) return;
    const int n = idx / Kd, k = idx - n * Kd;
    unsigned short a, b;
    split2(W[(size_t)k * Nd + n], a, b);
    out[idx]      = __ushort_as_bfloat16(a);
    out[NK + idx] = __ushort_as_bfloat16(b);
}
// input split (natural row-major): dst[2][n]
__global__ void isplit(const float* __restrict__ src, __nv_bfloat16* __restrict__ dst, int n) {
    const int i = blockIdx.x * blockDim.x + threadIdx.x;
    if (i >= n) return;
    unsigned short a, b;
    split2(src[i], a, b);
    dst[i]     = __ushort_as_bfloat16(a);
    dst[n + i] = __ushort_as_bfloat16(b);
}

// bu[k] = dot(sim_w row k, sim_b); c0 = ||sim_b||^2
__global__ void buk(const float* __restrict__ simw, const float* __restrict__ simb,
                    float* __restrict__ bu, float* __restrict__ c0)
{
    const int warp = (blockIdx.x * blockDim.x + threadIdx.x) >> 5;
    const int lane = threadIdx.x & 31;
    if (warp > H_) return;
    const float4* a = (warp < H_) ? (const float4*)(simw + (size_t)warp * H_)
                                  : (const float4*)simb;
    const float4* b = (const float4*)simb;
    float s = 0.f;
    #pragma unroll
    for (int q = 0; q < 4; q++) {
        float4 x = a[lane + q * 32], y = b[lane + q * 32];
        s += x.x * y.x + x.y * y.y + x.z * y.z + x.w * y.w;
    }
    #pragma unroll
    for (int o = 16; o; o >>= 1) s += __shfl_down_sync(0xffffffffu, s, o);
    if (lane == 0) {
        if (warp < H_) bu[warp] = s;
        else           c0[0] = s;
    }
}

// ---------------- HMMA GEMM: D[M,N] = A[M,K] @ Ws^T ----------------
// AMODE: 0 A = split planes As[2][M][K]; 1 gather split [objs|preds|objs] (K=384);
//        2 A = fp32 Af scaled by 1/denom[m] (runtime split)
// OMODE: 0 fp32 C; 1 split planes Cs[2][M][N]; 2 split N=1152 -> cand / out_newp / cand+T (fp32)
#define APITCH 80
#define PLANE  (128 * APITCH)                 // 10240 B
#define SMEMB  (8 * PLANE)                    // 81920 B

template<int AMODE, int OMODE, bool RELU, bool HASBIAS>
__global__ __launch_bounds__(256, 2)
void mmak(const __nv_bfloat16* __restrict__ As, const float* __restrict__ Af,
          const __nv_bfloat16* __restrict__ Wt,
          const float* __restrict__ bias, float* __restrict__ Cf,
          __nv_bfloat16* __restrict__ Cs,
          int M, int N, int K,
          const __nv_bfloat16* __restrict__ objs, const __nv_bfloat16* __restrict__ preds,
          const int* __restrict__ edges, const float* __restrict__ denomv,
          float* __restrict__ outp, float* __restrict__ candp)
{
    extern __shared__ __align__(16) unsigned char sm[];
    const int tid = threadIdx.x;
    const int lane = tid & 31, wid = tid >> 5;
    const int wr = wid >> 2, wc = wid & 3;
    const int bm = blockIdx.y * 128, bn = blockIdx.x * 128;
    const size_t MK = (size_t)M * K, NK = (size_t)N * K, MN = (size_t)M * N;
    const uint32_t sb = smem_u32(sm);
    const int arow = lane >> 2, acol = (lane & 3) << 1;
    const int t8 = lane & 7, quad = lane >> 3;

    const uint32_t aoff = (uint32_t)(wr * 64 + t8 + ((quad & 1) << 3)) * APITCH + ((quad >> 1) << 4);
    const uint32_t boff = 2 * PLANE +
        (uint32_t)(wc * 32 + t8 + ((quad >> 1) << 3)) * APITCH + ((quad & 1) << 4);

    float acc[4][4][4];
    #pragma unroll
    for (int i = 0; i < 4; i++)
        #pragma unroll
        for (int j = 0; j < 4; j++)
            #pragma unroll
            for (int q = 0; q < 4; q++) acc[i][j][q] = 0.f;

    float4 pf[4];  // AMODE2 prefetch

    auto stageAsync = [&](int k0, int b) {
        const uint32_t smA = sb + b * 4 * PLANE;
        const uint32_t smB = smA + 2 * PLANE;
        if (AMODE == 0) {
            #pragma unroll
            for (int it = 0; it < 4; it++) {
                const int idx = (it << 8) + tid;
                const int p = idx >> 9, r = (idx >> 2) & 127, seg = idx & 3;
                const int gm = bm + r;
                const int gmc = gm < M ? gm : M - 1;
                const __nv_bfloat16* src = As + (size_t)p * MK + (size_t)gmc * K + k0 + seg * 8;
                cpa16(smA + p * PLANE + r * APITCH + seg * 16, src, gm < M ? 16u : 0u);
            }
        } else if (AMODE == 1) {
            #pragma unroll
            for (int it = 0; it < 4; it++) {
                const int idx = (it << 8) + tid;
                const int p = idx >> 9, r = (idx >> 2) & 127, seg = idx & 3;
                const int gm = bm + r;
                const int gmc = gm < M ? gm : M - 1;
                const __nv_bfloat16* src;
                if (k0 < DIN_)
                    src = objs + (size_t)p * ((size_t)NOBJ * DIN_)
                        + (size_t)edges[2 * gmc] * DIN_ + k0 + seg * 8;
                else if (k0 < 2 * DIN_)
                    src = preds + (size_t)p * ((size_t)NTRI * DIN_)
                        + (size_t)gmc * DIN_ + (k0 - DIN_) + seg * 8;
                else
                    src = objs + (size_t)p * ((size_t)NOBJ * DIN_)
                        + (size_t)edges[2 * gmc + 1] * DIN_ + (k0 - 2 * DIN_) + seg * 8;
                cpa16(smA + p * PLANE + r * APITCH + seg * 16, src, gm < M ? 16u : 0u);
            }
        }
        #pragma unroll
        for (int it = 0; it < 4; it++) {
            const int idx = (it << 8) + tid;
            const int p = idx >> 9, n = (idx >> 2) & 127, seg = idx & 3;
            const __nv_bfloat16* src = Wt + (size_t)p * NK + (size_t)(bn + n) * K + k0 + seg * 8;
            cpa16(smB + p * PLANE + n * APITCH + seg * 16, src, 16u);
        }
        CPA_COMMIT();
    };

    auto loadA2 = [&](int k0) {
        #pragma unroll
        for (int it = 0; it < 4; it++) {
            const int idx = (it << 8) + tid;
            const int m = idx >> 3, q = idx & 7;
            const int gm = bm + m;
            float4 v = make_float4(0.f, 0.f, 0.f, 0.f);
            if (gm < M) {
                v = *(const float4*)(Af + (size_t)gm * K + k0 + (q << 2));
                const float sc = __fdividef(1.f, denomv[gm]);
                v.x *= sc; v.y *= sc; v.z *= sc; v.w *= sc;
            }
            pf[it] = v;
        }
    };
    auto stsA2 = [&](int b) {
        unsigned char* smA = sm + b * 4 * PLANE;
        #pragma unroll
        for (int it = 0; it < 4; it++) {
            const int idx = (it << 8) + tid;
            const int m = idx >> 3, q = idx & 7;
            unsigned short h[4], l[4];
            split2(pf[it].x, h[0], l[0]); split2(pf[it].y, h[1], l[1]);
            split2(pf[it].z, h[2], l[2]); split2(pf[it].w, h[3], l[3]);
            const int boff2 = m * APITCH + (q << 3);
            *(uint2*)(smA + boff2) = make_uint2((uint32_t)h[0] | ((uint32_t)h[1] << 16),
                                                (uint32_t)h[2] | ((uint32_t)h[3] << 16));
            *(uint2*)(smA + PLANE + boff2) = make_uint2((uint32_t)l[0] | ((uint32_t)l[1] << 16),
                                                        (uint32_t)l[2] | ((uint32_t)l[3] << 16));
        }
    };

    auto compute = [&](int b) {
        const uint32_t buf = sb + b * 4 * PLANE;
        #pragma unroll
        for (int s = 0; s < 2; s++) {
            const uint32_t ksb = s * 32;
            uint32_t af[2][4][4];
            #pragma unroll
            for (int p = 0; p < 2; p++)
                #pragma unroll
                for (int i = 0; i < 4; i++)
                    ldsm4(af[p][i], buf + p * PLANE + aoff + i * 16 * APITCH + ksb);
            uint32_t bfr[2][4][2];
            #pragma unroll
            for (int p = 0; p < 2; p++)
                #pragma unroll
                for (int jj = 0; jj < 2; jj++)
                    ldsm4(&bfr[p][jj * 2][0], buf + p * PLANE + boff + jj * 16 * APITCH + ksb);
            #pragma unroll
            for (int j = 0; j < 4; j++)
                #pragma unroll
                for (int i = 0; i < 4; i++)
                    mma16816(acc[i][j], af[0][i], bfr[0][j][0], bfr[0][j][1]);
            #pragma unroll
            for (int j = 0; j < 4; j++)
                #pragma unroll
                for (int i = 0; i < 4; i++)
                    mma16816(acc[i][j], af[1][i], bfr[0][j][0], bfr[0][j][1]);
            #pragma unroll
            for (int j = 0; j < 4; j++)
                #pragma unroll
                for (int i = 0; i < 4; i++)
                    mma16816(acc[i][j], af[0][i], bfr[1][j][0], bfr[1][j][1]);
        }
    };

    const int nch = K >> 5;
    stageAsync(0, 0);
    if (AMODE == 2) { loadA2(0); stsA2(0); }
    CPA_WAIT0();
    __syncthreads();

    for (int ch = 0; ch < nch; ch++) {
        const int b = ch & 1;
        const bool nxt = (ch + 1) < nch;
        if (nxt) {
            stageAsync((ch + 1) << 5, b ^ 1);
            if (AMODE == 2) loadA2((ch + 1) << 5);
        }
        compute(b);
        if (nxt && AMODE == 2) stsA2(b ^ 1);
        CPA_WAIT0();
        __syncthreads();
    }

    // ---- epilogue ----
    #pragma unroll
    for (int i = 0; i < 4; i++)
        #pragma unroll
        for (int j = 0; j < 4; j++) {
            const int gm0 = bm + wr * 64 + i * 16 + arow;
            const int gn  = bn + wc * 32 + j * 8 + acol;
            float2 bb = make_float2(0.f, 0.f);
            if (HASBIAS) bb = *(const float2*)&bias[gn];
            #pragma unroll
            for (int h = 0; h < 2; h++) {
                const int m = gm0 + h * 8;
                if (m < M) {
                    float x0 = acc[i][j][2 * h]     + bb.x;
                    float x1 = acc[i][j][2 * h + 1] + bb.y;
                    if (RELU) { x0 = fmaxf(x0, 0.f); x1 = fmaxf(x1, 0.f); }
                    if (OMODE == 0) {
                        *(float2*)(Cf + (size_t)m * N + gn) = make_float2(x0, x1);
                    } else if (OMODE == 1) {
                        unsigned short h0, l0, h1, l1;
                        split2(x0, h0, l0); split2(x1, h1, l1);
                        *(uint32_t*)(Cs + (size_t)m * N + gn)      = (uint32_t)h0 | ((uint32_t)h1 << 16);
                        *(uint32_t*)(Cs + MN + (size_t)m * N + gn) = (uint32_t)l0 | ((uint32_t)l1 << 16);
                    } else {
                        float* dst;
                        if (gn < H_)              dst = candp + (size_t)m * H_ + gn;
                        else if (gn < H_ + DOUT_) dst = outp + (size_t)m * DOUT_ + (gn - H_);
                        else                      dst = candp + (size_t)(NTRI + m) * H_ + (gn - H_ - DOUT_);
                        *(float2*)dst = make_float2(x0, x1);
                    }
                }
            }
        }
}

// ---------------- softmax / pooling kernels ----------------
__device__ __forceinline__ unsigned fenc(float f) {
    unsigned u = __float_as_uint(f);
    return (u & 0x80000000u) ? ~u : (u | 0x80000000u);
}
__device__ __forceinline__ float fdec(unsigned e) {
    unsigned u = (e & 0x80000000u) ? (e & 0x7fffffffu) : ~e;
    return __uint_as_float(u);
}

// z[i] = (prevs_hi[i]+prevs_lo[i]) . bu + c0 ; seed mkey
__global__ void zk3(const __nv_bfloat16* __restrict__ prevs, const float* __restrict__ bu,
                    const float* __restrict__ c0, float* __restrict__ z,
                    unsigned* __restrict__ mkey)
{
    const int row = (blockIdx.x * blockDim.x + threadIdx.x) >> 5;
    const int lane = threadIdx.x & 31;
    if (row >= NOBJ) return;
    const size_t PS = (size_t)NOBJ * H_;
    const uint2* ph = (const uint2*)(prevs + (size_t)row * H_);
    const uint2* pl = (const uint2*)(prevs + PS + (size_t)row * H_);
    float s = 0.f;
    #pragma unroll
    for (int q = 0; q < 4; q++) {
        const int t = lane + q * 32;
        uint2 a = ph[t], b = pl[t];
        float4 w4 = *(const float4*)&bu[t * 4];
        float2 a0 = bf2(a.x), a1 = bf2(a.y), b0 = bf2(b.x), b1 = bf2(b.y);
        s += (a0.x + b0.x) * w4.x + (a0.y + b0.y) * w4.y
           + (a1.x + b1.x) * w4.z + (a1.y + b1.y) * w4.w;
    }
    #pragma unroll
    for (int o = 16; o; o >>= 1) s += __shfl_down_sync(0xffffffffu, s, o);
    if (lane == 0) {
        const float v = s + c0[0];
        z[row] = v;
        mkey[row] = fenc(v);
    }
}

// scores[e] = cand[e] . (us_hi+us_lo)[idx] + z[idx];  atomicMax into mkey
__global__ void scorek2(const float* __restrict__ cand, const __nv_bfloat16* __restrict__ us,
                        const float* __restrict__ z, const int* __restrict__ edges,
                        float* __restrict__ scores, unsigned* __restrict__ mkey)
{
    const int e = (blockIdx.x * blockDim.x + threadIdx.x) >> 5;
    const int lane = threadIdx.x & 31;
    if (e >= 2 * NTRI) return;
    const int idx = (e < NTRI) ? edges[2 * e] : edges[2 * (e - NTRI) + 1];
    const size_t PS = (size_t)NOBJ * H_;
    const float4* a = (const float4*)(cand + (size_t)e * H_);
    const uint2* uh = (const uint2*)(us + (size_t)idx * H_);
    const uint2* ul = (const uint2*)(us + PS + (size_t)idx * H_);
    float s = 0.f;
    #pragma unroll
    for (int q = 0; q < 4; q++) {
        const int t = lane + q * 32;
        float4 x = a[t];
        uint2 hu = uh[t], lu = ul[t];
        float2 h0 = bf2(hu.x), h1 = bf2(hu.y), l0 = bf2(lu.x), l1 = bf2(lu.y);
        s += x.x * (h0.x + l0.x) + x.y * (h0.y + l0.y)
           + x.z * (h1.x + l1.x) + x.w * (h1.y + l1.y);
    }
    #pragma unroll
    for (int o = 16; o; o >>= 1) s += __shfl_down_sync(0xffffffffu, s, o);
    if (lane == 0) {
        const float sc = s + z[idx];
        scores[e] = sc;
        atomicMax(mkey + idx, fenc(sc));
    }
}

__global__ void zerok(float* __restrict__ p, size_t n)
{
    size_t i = (size_t)blockIdx.x * blockDim.x + threadIdx.x;
    const size_t stride = (size_t)gridDim.x * blockDim.x;
    for (; i < n; i += stride) p[i] = 0.f;
}

__global__ void dinitk(const float* __restrict__ z, const unsigned* __restrict__ mkey,
                       float* __restrict__ denom)
{
    const int i = blockIdx.x * blockDim.x + threadIdx.x;
    if (i < NOBJ) denom[i] = expf(z[i] - fdec(mkey[i]));
}

// fused: w = exp(score - m); denom += w; pooled[idx] += w * cand[e]
__global__ void poolwk(const float* __restrict__ scores, const unsigned* __restrict__ mkey,
                       const int* __restrict__ edges, const float* __restrict__ cand,
                       float* __restrict__ denom, float* __restrict__ pooled)
{
    const int e = (blockIdx.x * blockDim.x + threadIdx.x) >> 5;
    const int lane = threadIdx.x & 31;
    if (e >= 2 * NTRI) return;
    const int idx = (e < NTRI) ? edges[2 * e] : edges[2 * (e - NTRI) + 1];
    float ww = 0.f;
    if (lane == 0) {
        ww = expf(scores[e] - fdec(mkey[idx]));
        atomicAdd(denom + idx, ww);
    }
    ww = __shfl_sync(0xffffffffu, ww, 0);
    const float4* src = (const float4*)(cand + (size_t)e * H_);
    float* dst = pooled + (size_t)idx * H_;
    #pragma unroll
    for (int q = 0; q < 4; q++) {
        float4 v = src[lane + q * 32];
        float* d = dst + (size_t)(lane + q * 32) * 4;
        asm volatile("red.global.add.v4.f32 [%0], {%1, %2, %3, %4};"
                     :: "l"(d), "f"(v.x * ww), "f"(v.y * ww), "f"(v.z * ww), "f"(v.w * ww)
                     : "memory");
    }
}

extern "C" void kernel_launch(void* const* d_in, const int* in_sizes, int n_in,
                              void* d_out, int out_size)
{
    const float* obj    = (const float*)d_in[0];
    const float* pred   = (const float*)d_in[1];
    const int*   edges  = (const int*)d_in[2];
    const float* n1_w1  = (const float*)d_in[3];
    const float* n1_b1  = (const float*)d_in[4];
    const float* n1_w2  = (const float*)d_in[5];
    const float* n1_b2  = (const float*)d_in[6];
    const float* n2_w1  = (const float*)d_in[7];
    const float* n2_b1  = (const float*)d_in[8];
    const float* n2_w2  = (const float*)d_in[9];
    const float* n2_b2  = (const float*)d_in[10];
    const float* proj_w = (const float*)d_in[11];
    const float* proj_b = (const float*)d_in[12];
    const float* sim_w  = (const float*)d_in[13];
    const float* sim_b  = (const float*)d_in[14];

    float* out        = (float*)d_out;
    float* out_newobj = out;
    float* out_newp   = out + (size_t)NOBJ * DOUT_;

    float *cand, *pooled, *z, *scores, *denom, *bu, *c0;
    unsigned* mkey;
    __nv_bfloat16 *objs, *preds, *h1s, *prevs, *us, *h2s, *simws, *Ss;
    __nv_bfloat16 *wproj, *wn1a, *wn1b, *wn2a, *wn2b;
    cudaGetSymbolAddress((void**)&cand, g_cand);
    cudaGetSymbolAddress((void**)&pooled, g_pooled);
    cudaGetSymbolAddress((void**)&z, g_z);
    cudaGetSymbolAddress((void**)&mkey, g_mkey);
    cudaGetSymbolAddress((void**)&scores, g_scores);
    cudaGetSymbolAddress((void**)&denom, g_denom);
    cudaGetSymbolAddress((void**)&bu, g_bu);
    cudaGetSymbolAddress((void**)&c0, g_c0);
    cudaGetSymbolAddress((void**)&objs, g_objs);
    cudaGetSymbolAddress((void**)&preds, g_preds);
    cudaGetSymbolAddress((void**)&h1s, g_h1s);
    cudaGetSymbolAddress((void**)&prevs, g_prevs);
    cudaGetSymbolAddress((void**)&us, g_us);
    cudaGetSymbolAddress((void**)&h2s, g_h2s);
    cudaGetSymbolAddress((void**)&simws, g_simws);
    cudaGetSymbolAddress((void**)&Ss, g_Ss);
    cudaGetSymbolAddress((void**)&wproj, g_wproj);
    cudaGetSymbolAddress((void**)&wn1a, g_wn1a);
    cudaGetSymbolAddress((void**)&wn1b, g_wn1b);
    cudaGetSymbolAddress((void**)&wn2a, g_wn2a);
    cudaGetSymbolAddress((void**)&wn2b, g_wn2b);

    cudaFuncSetAttribute(mmak<0,1,false,true>,  cudaFuncAttributeMaxDynamicSharedMemorySize, SMEMB);
    cudaFuncSetAttribute(mmak<0,1,false,false>, cudaFuncAttributeMaxDynamicSharedMemorySize, SMEMB);
    cudaFuncSetAttribute(mmak<1,1,true,true>,   cudaFuncAttributeMaxDynamicSharedMemorySize, SMEMB);
    cudaFuncSetAttribute(mmak<0,2,true,true>,   cudaFuncAttributeMaxDynamicSharedMemorySize, SMEMB);
    cudaFuncSetAttribute(mmak<2,1,true,true>,   cudaFuncAttributeMaxDynamicSharedMemorySize, SMEMB);
    cudaFuncSetAttribute(mmak<0,0,true,true>,   cudaFuncAttributeMaxDynamicSharedMemorySize, SMEMB);

    const int gO = (NOBJ + 127) / 128;   // 391
    const int gT = (NTRI + 127) / 128;   // 782
    const dim3 blk(256);

    // ncu profiles launch #6 (-s 5 -c 1): first 5 = prerequisites of the gather GEMM.
    wsplitT<<<(512 * 384 + 255) / 256, 256>>>(n1_w1, wn1a, 384, 512);          // 1
    isplit<<<(NOBJ * DIN_ + 255) / 256, 256>>>(obj, objs, NOBJ * DIN_);        // 2
    isplit<<<(NTRI * DIN_ + 255) / 256, 256>>>(pred, preds, NTRI * DIN_);      // 3
    wsplitT<<<(1152 * 512 + 255) / 256, 256>>>(n1_w2, wn1b, 512, 1152);        // 4
    wsplitT<<<(512 * 128 + 255) / 256, 256>>>(proj_w, wproj, 128, 512);        // 5

    // 6: triple MLP layer 1 (gather GEMM) — profiled
    mmak<1,1,true,true><<<dim3(4, gT), blk, SMEMB>>>(nullptr, nullptr, wn1a, n1_b1, nullptr, h1s,
        NTRI, 512, 384, objs, preds, edges, nullptr, nullptr, nullptr);

    // sim-side precompute: S = sim_w@sim_w^T (split), bu, c0
    isplit<<<(512 * 512 + 255) / 256, 256>>>(sim_w, simws, 512 * 512);
    buk<<<65, 256>>>(sim_w, sim_b, bu, c0);
    mmak<0,1,false,false><<<dim3(4, 4), blk, SMEMB>>>(simws, nullptr, simws, nullptr, nullptr, Ss,
        512, 512, 512, nullptr, nullptr, nullptr, nullptr, nullptr, nullptr);
    wsplitT<<<(512 * 512 + 255) / 256, 256>>>(n2_w1, wn2a, 512, 512);
    wsplitT<<<(512 * 128 + 255) / 256, 256>>>(n2_w2, wn2b, 512, 128);

    // triple MLP layer 2 (split outputs into cand / new_p)
    mmak<0,2,true,true><<<dim3(9, gT), blk, SMEMB>>>(h1s, nullptr, wn1b, n1_b2, nullptr, nullptr,
        NTRI, 1152, 512, nullptr, nullptr, nullptr, nullptr, out_newp, cand);

    // object-side: prev projection, then u = prev@S + bu directly
    mmak<0,1,false,true><<<dim3(4, gO), blk, SMEMB>>>(objs, nullptr, wproj, proj_b, nullptr, prevs,
        NOBJ, 512, 128, nullptr, nullptr, nullptr, nullptr, nullptr, nullptr);
    zk3<<<(NOBJ * 32 + 255) / 256, 256>>>(prevs, bu, c0, z, mkey);
    mmak<0,1,false,true><<<dim3(4, gO), blk, SMEMB>>>(prevs, nullptr, Ss, bu, nullptr, us,
        NOBJ, 512, 512, nullptr, nullptr, nullptr, nullptr, nullptr, nullptr);

    // attention scores + segment softmax (wk fused into pool)
    scorek2<<<(2 * NTRI + 7) / 8, 256>>>(cand, us, z, edges, scores, mkey);
    zerok<<<2048, 256>>>(pooled, (size_t)NOBJ * H_);
    dinitk<<<(NOBJ + 255) / 256, 256>>>(z, mkey, denom);
    poolwk<<<(2 * NTRI + 7) / 8, 256>>>(scores, mkey, edges, cand, denom, pooled);

    // output MLP
    mmak<2,1,true,true><<<dim3(4, gO), blk, SMEMB>>>(nullptr, pooled, wn2a, n2_b1, nullptr, h2s,
        NOBJ, 512, 512, nullptr, nullptr, nullptr, denom, nullptr, nullptr);
    mmak<0,0,true,true><<<dim3(1, gO), blk, SMEMB>>>(h2s, nullptr, wn2b, n2_b2, out_newobj, nullptr,
        NOBJ, 128, 512, nullptr, nullptr, nullptr, nullptr, nullptr, nullptr);
}